// round 1
// baseline (speedup 1.0000x reference)
#include <cuda_runtime.h>
#include <math.h>
#include <stdint.h>

// Problem constants
#define BB   128
#define SS   400
#define EE   512
#define HH   512
#define VV   50257
#define NOOV 50
#define VEXTN (VV + NOOV)   // 50307

// ---------------------------------------------------------------------------
// Scratch (device globals: allocation-free per harness rules)
// ---------------------------------------------------------------------------
__device__ float g_x[BB * EE];
__device__ float g_gates[BB * 4 * HH];
__device__ float g_h1[BB * HH];
__device__ float g_c1[BB * HH];
__device__ float g_decfea[BB * HH];
__device__ float g_ctx[BB * HH];
__device__ float g_decout[BB * HH];
__device__ float g_e[BB * SS];
__device__ float g_attn[BB * SS];
__device__ float g_pgen[BB];
__device__ float g_rowm[BB];
__device__ float g_rows[BB];
__device__ float g_logits[(size_t)BB * VV];   // 25.7 MB

__device__ __forceinline__ float sigmoidf_(float x) {
    return 1.f / (1.f + expf(-x));
}

// ---------------------------------------------------------------------------
// Generic tiled SGEMM:  C[M,N] = Acat[M,K] * Bcat[N,K]^T + bias[N]
// Acat[m,k] = (k < KA0) ? A0[m*KA0+k] : A1[m*(K-KA0)+(k-KA0)]   (A1 may be null)
// Bcat[n,k] analogous. All row-major fp32.
// ---------------------------------------------------------------------------
template <int BM, int BN, int BK, int TM, int TN>
__global__ void sgemm_cat(int M, int N, int K,
                          const float* __restrict__ A0, int KA0,
                          const float* __restrict__ A1,
                          const float* __restrict__ B0, int KB0,
                          const float* __restrict__ B1,
                          const float* __restrict__ bias,
                          float* __restrict__ C)
{
    constexpr int THREADS = (BM / TM) * (BN / TN);
    __shared__ float As[BK][BM + 4];
    __shared__ float Bs[BK][BN + 4];

    const int tid  = threadIdx.x;
    const int m0   = blockIdx.y * BM;
    const int n0   = blockIdx.x * BN;
    const int tcol = tid % (BN / TN);
    const int trow = tid / (BN / TN);
    const int KA1  = K - KA0;
    const int KB1  = K - KB0;

    float acc[TM][TN];
#pragma unroll
    for (int i = 0; i < TM; i++)
#pragma unroll
        for (int j = 0; j < TN; j++) acc[i][j] = 0.f;

    for (int k0 = 0; k0 < K; k0 += BK) {
        // Load A tile (BM x BK) into As transposed
        for (int idx = tid; idx < BM * BK; idx += THREADS) {
            int m = idx / BK, kk = idx % BK;
            int k = k0 + kk;
            int gm = m0 + m;
            float v = 0.f;
            if (gm < M) {
                v = (k < KA0) ? A0[(size_t)gm * KA0 + k]
                              : A1[(size_t)gm * KA1 + (k - KA0)];
            }
            As[kk][m] = v;
        }
        // Load B tile (BN x BK) into Bs transposed
        for (int idx = tid; idx < BN * BK; idx += THREADS) {
            int n = idx / BK, kk = idx % BK;
            int k = k0 + kk;
            int gn = n0 + n;
            float v = 0.f;
            if (gn < N) {
                v = (k < KB0) ? B0[(size_t)gn * KB0 + k]
                              : B1[(size_t)gn * KB1 + (k - KB0)];
            }
            Bs[kk][n] = v;
        }
        __syncthreads();

#pragma unroll
        for (int kk = 0; kk < BK; kk++) {
            float a[TM], b[TN];
#pragma unroll
            for (int i = 0; i < TM; i++) a[i] = As[kk][trow * TM + i];
#pragma unroll
            for (int j = 0; j < TN; j++) b[j] = Bs[kk][tcol * TN + j];
#pragma unroll
            for (int i = 0; i < TM; i++)
#pragma unroll
                for (int j = 0; j < TN; j++) acc[i][j] += a[i] * b[j];
        }
        __syncthreads();
    }

#pragma unroll
    for (int i = 0; i < TM; i++) {
        int gm = m0 + trow * TM + i;
        if (gm >= M) continue;
#pragma unroll
        for (int j = 0; j < TN; j++) {
            int gn = n0 + tcol * TN + j;
            if (gn < N) {
                float v = acc[i][j];
                if (bias) v += bias[gn];
                C[(size_t)gm * N + gn] = v;
            }
        }
    }
}

// ---------------------------------------------------------------------------
// LSTM elementwise: gates (B x 4H, bias b_ih already applied) + b_hh -> h1,c1
// ---------------------------------------------------------------------------
__global__ void lstm_elem(const float* __restrict__ gates,
                          const float* __restrict__ b_hh,
                          const float* __restrict__ c0,
                          float* __restrict__ h1, float* __restrict__ c1,
                          float* __restrict__ out_h1, float* __restrict__ out_c1)
{
    int idx = blockIdx.x * blockDim.x + threadIdx.x;
    if (idx >= BB * HH) return;
    int b = idx / HH, j = idx % HH;
    const float* g = gates + (size_t)b * 4 * HH;
    float iv = sigmoidf_(g[j]          + b_hh[j]);
    float fv = sigmoidf_(g[HH + j]     + b_hh[HH + j]);
    float gv = tanhf(    g[2 * HH + j] + b_hh[2 * HH + j]);
    float ov = sigmoidf_(g[3 * HH + j] + b_hh[3 * HH + j]);
    float c = fv * c0[idx] + iv * gv;
    float h = ov * tanhf(c);
    h1[idx] = h; c1[idx] = c;
    out_h1[idx] = h; out_c1[idx] = c;
}

// ---------------------------------------------------------------------------
// Attention energies: e[b,s] = v_att . tanh(sf[b,s,:] + dec_fea[b,:] + wc*cov[b,s])
// one warp per (b,s) row
// ---------------------------------------------------------------------------
__global__ void attn_e_kernel(const float* __restrict__ sf,
                              const float* __restrict__ dec_fea,
                              const float* __restrict__ cov,
                              const float* __restrict__ mask,
                              const float* __restrict__ v_att,
                              const float* __restrict__ w_c,
                              float* __restrict__ e)
{
    int gwarp = (blockIdx.x * blockDim.x + threadIdx.x) >> 5;
    int lane = threadIdx.x & 31;
    if (gwarp >= BB * SS) return;
    int b = gwarp / SS;
    float cadd = w_c[0] * cov[gwarp];

    const float4* row = (const float4*)(sf + (size_t)gwarp * HH);
    const float4* df  = (const float4*)(dec_fea + (size_t)b * HH);
    const float4* va  = (const float4*)(v_att);

    float acc = 0.f;
#pragma unroll
    for (int i = 0; i < HH / 128; i++) {   // 4 iterations of float4
        float4 x = row[i * 32 + lane];
        float4 d = df[i * 32 + lane];
        float4 v = va[i * 32 + lane];
        acc += tanhf(x.x + d.x + cadd) * v.x;
        acc += tanhf(x.y + d.y + cadd) * v.y;
        acc += tanhf(x.z + d.z + cadd) * v.z;
        acc += tanhf(x.w + d.w + cadd) * v.w;
    }
#pragma unroll
    for (int off = 16; off; off >>= 1) acc += __shfl_xor_sync(0xffffffffu, acc, off);
    if (lane == 0) e[gwarp] = (mask[gwarp] > 0.f) ? acc : -1.0e9f;
}

// ---------------------------------------------------------------------------
// Softmax over S per batch row, with mask renorm + coverage update
// ---------------------------------------------------------------------------
__global__ void softmax_s_kernel(const float* __restrict__ e,
                                 const float* __restrict__ mask,
                                 const float* __restrict__ cov,
                                 float* __restrict__ attn,
                                 float* __restrict__ out_attn,
                                 float* __restrict__ out_cov)
{
    int b = blockIdx.x;
    int tid = threadIdx.x;           // 512 threads
    __shared__ float sh[SS];
    __shared__ float r1[512];
    __shared__ float r2[512];

    float m = -3.0e38f;
    for (int s = tid; s < SS; s += 512) m = fmaxf(m, e[b * SS + s]);
    r1[tid] = m; __syncthreads();
    for (int off = 256; off; off >>= 1) {
        if (tid < off) r1[tid] = fmaxf(r1[tid], r1[tid + off]);
        __syncthreads();
    }
    m = r1[0];
    __syncthreads();

    float P = 0.f, Q = 0.f;
    for (int s = tid; s < SS; s += 512) {
        float p = expf(e[b * SS + s] - m);
        sh[s] = p;
        P += p;
        Q += p * mask[b * SS + s];
    }
    r1[tid] = P; r2[tid] = Q; __syncthreads();
    for (int off = 256; off; off >>= 1) {
        if (tid < off) { r1[tid] += r1[tid + off]; r2[tid] += r2[tid + off]; }
        __syncthreads();
    }
    P = r1[0]; Q = r2[0];
    float denom = Q / P + 1e-12f;

    for (int s = tid; s < SS; s += 512) {
        float a = sh[s] * mask[b * SS + s] / P / denom;
        attn[b * SS + s] = a;
        out_attn[b * SS + s] = a;
        out_cov[b * SS + s] = cov[b * SS + s] + a;
    }
}

// ---------------------------------------------------------------------------
// Context: ctx[b,h] = sum_s attn[b,s] * states[b,s,h]. grid (B, 2), 256 thr
// ---------------------------------------------------------------------------
__global__ void ctx_kernel(const float* __restrict__ attn,
                           const float* __restrict__ states,
                           float* __restrict__ ctx)
{
    int b = blockIdx.x;
    int h = blockIdx.y * 256 + threadIdx.x;
    __shared__ float sa[SS];
    for (int s = threadIdx.x; s < SS; s += 256) sa[s] = attn[b * SS + s];
    __syncthreads();

    const float* st = states + (size_t)b * SS * HH + h;
    float a0 = 0.f, a1 = 0.f, a2 = 0.f, a3 = 0.f;
    for (int s = 0; s < SS; s += 4) {
        a0 += sa[s]     * st[(size_t)(s)     * HH];
        a1 += sa[s + 1] * st[(size_t)(s + 1) * HH];
        a2 += sa[s + 2] * st[(size_t)(s + 2) * HH];
        a3 += sa[s + 3] * st[(size_t)(s + 3) * HH];
    }
    ctx[b * HH + h] = (a0 + a1) + (a2 + a3);
}

// ---------------------------------------------------------------------------
// p_gen = sigmoid(dec_out . W_pg + b_pg); also copy dec_out to output
// ---------------------------------------------------------------------------
__global__ void pgen_kernel(const float* __restrict__ dec_out,
                            const float* __restrict__ W_pg,
                            const float* __restrict__ b_pg,
                            float* __restrict__ pgen,
                            float* __restrict__ out_pgen,
                            float* __restrict__ out_dec)
{
    int b = blockIdx.x;
    int tid = threadIdx.x;            // 128 threads
    float acc = 0.f;
    for (int j = tid; j < HH; j += 128) {
        float d = dec_out[b * HH + j];
        out_dec[b * HH + j] = d;
        acc += d * W_pg[j];
    }
    __shared__ float red[4];
#pragma unroll
    for (int off = 16; off; off >>= 1) acc += __shfl_xor_sync(0xffffffffu, acc, off);
    if ((tid & 31) == 0) red[tid >> 5] = acc;
    __syncthreads();
    if (tid == 0) {
        float t = red[0] + red[1] + red[2] + red[3];
        float p = sigmoidf_(t + b_pg[0]);
        pgen[b] = p;
        out_pgen[b] = p;
    }
}

// ---------------------------------------------------------------------------
// Row max + sum(exp) over vocab (online), one block per batch row
// ---------------------------------------------------------------------------
__global__ void vocab_stats_kernel(const float* __restrict__ logits,
                                   float* __restrict__ rowm,
                                   float* __restrict__ rows)
{
    int b = blockIdx.x;
    int tid = threadIdx.x;    // 512
    float m = -3.0e38f, s = 0.f;
    for (int v = tid; v < VV; v += 512) {
        float x = logits[(size_t)b * VV + v];
        if (x > m) {
            s = s * expf(m - x) + 1.f;
            m = x;
        } else {
            s += expf(x - m);
        }
    }
    __shared__ float sm[512], ssum[512];
    sm[tid] = m; ssum[tid] = s; __syncthreads();
    for (int off = 256; off; off >>= 1) {
        if (tid < off) {
            float m2 = sm[tid + off], s2 = ssum[tid + off];
            float M = fmaxf(sm[tid], m2);
            ssum[tid] = ssum[tid] * expf(sm[tid] - M) + s2 * expf(m2 - M);
            sm[tid] = M;
        }
        __syncthreads();
    }
    if (tid == 0) { rowm[b] = sm[0]; rows[b] = ssum[0]; }
}

// ---------------------------------------------------------------------------
// Write final vocab distribution (p_gen * softmax, OOV zeros)
// ---------------------------------------------------------------------------
__global__ void final_vocab_kernel(const float* __restrict__ logits,
                                   const float* __restrict__ rowm,
                                   const float* __restrict__ rows,
                                   const float* __restrict__ pgen,
                                   float* __restrict__ outf)
{
    long idx = (long)blockIdx.x * blockDim.x + threadIdx.x;
    if (idx >= (long)BB * VEXTN) return;
    int b = (int)(idx / VEXTN);
    int n = (int)(idx % VEXTN);
    float val = 0.f;
    if (n < VV) {
        val = pgen[b] * expf(logits[(size_t)b * VV + n] - rowm[b]) / rows[b];
    }
    outf[idx] = val;
}

// ---------------------------------------------------------------------------
// Copy-mechanism scatter: outf[b, ids[b,s]] += (1-p_gen[b]) * attn[b,s]
// ---------------------------------------------------------------------------
__global__ void scatter_kernel(const int* __restrict__ ids,
                               const float* __restrict__ attn,
                               const float* __restrict__ pgen,
                               float* __restrict__ outf)
{
    int idx = blockIdx.x * blockDim.x + threadIdx.x;
    if (idx >= BB * SS) return;
    int b = idx / SS;
    float v = (1.f - pgen[b]) * attn[idx];
    atomicAdd(&outf[(size_t)b * VEXTN + ids[idx]], v);
}

// ---------------------------------------------------------------------------
// Launcher
// ---------------------------------------------------------------------------
extern "C" void kernel_launch(void* const* d_in, const int* in_sizes, int n_in,
                              void* d_out, int out_size)
{
    const float* emb    = (const float*)d_in[0];
    const float* feed   = (const float*)d_in[1];
    const float* hidden = (const float*)d_in[2];   // (1,B,H)
    const float* ctx0   = (const float*)d_in[3];   // (1,B,H)
    const float* states = (const float*)d_in[4];
    const float* sfeat  = (const float*)d_in[5];
    const float* mask   = (const float*)d_in[6];
    const float* cov    = (const float*)d_in[7];
    const int*   srcids = (const int*)d_in[8];
    const float* W_ic   = (const float*)d_in[9];
    const float* b_ic   = (const float*)d_in[10];
    const float* W_ih   = (const float*)d_in[11];
    const float* W_hh   = (const float*)d_in[12];
    const float* b_ih   = (const float*)d_in[13];
    const float* b_hh   = (const float*)d_in[14];
    const float* W_dec  = (const float*)d_in[15];
    const float* b_att  = (const float*)d_in[16];
    const float* v_att  = (const float*)d_in[17];
    const float* w_c    = (const float*)d_in[18];
    const float* W_out  = (const float*)d_in[19];
    const float* b_out  = (const float*)d_in[20];
    const float* W_pg   = (const float*)d_in[21];
    const float* b_pg   = (const float*)d_in[22];
    const float* W_v    = (const float*)d_in[23];
    const float* b_v    = (const float*)d_in[24];

    float* out = (float*)d_out;
    float* out_final = out;
    float* out_pgen  = out_final + (size_t)BB * VEXTN;
    float* out_attn  = out_pgen + BB;
    float* out_cov   = out_attn + (size_t)BB * SS;
    float* out_h1    = out_cov + (size_t)BB * SS;
    float* out_c1    = out_h1 + (size_t)BB * HH;
    float* out_dec   = out_c1 + (size_t)BB * HH;

    float *px, *pgates, *ph1, *pc1, *pdecfea, *pctx, *pdecout;
    float *pe, *pattn, *ppgen, *prowm, *prows, *plogits;
    cudaGetSymbolAddress((void**)&px,      g_x);
    cudaGetSymbolAddress((void**)&pgates,  g_gates);
    cudaGetSymbolAddress((void**)&ph1,     g_h1);
    cudaGetSymbolAddress((void**)&pc1,     g_c1);
    cudaGetSymbolAddress((void**)&pdecfea, g_decfea);
    cudaGetSymbolAddress((void**)&pctx,    g_ctx);
    cudaGetSymbolAddress((void**)&pdecout, g_decout);
    cudaGetSymbolAddress((void**)&pe,      g_e);
    cudaGetSymbolAddress((void**)&pattn,   g_attn);
    cudaGetSymbolAddress((void**)&ppgen,   g_pgen);
    cudaGetSymbolAddress((void**)&prowm,   g_rowm);
    cudaGetSymbolAddress((void**)&prows,   g_rows);
    cudaGetSymbolAddress((void**)&plogits, g_logits);

    // 1) x = [emb|feed] @ W_ic^T + b_ic         (128 x 512, K=1024)
    sgemm_cat<64, 64, 16, 4, 4><<<dim3(EE / 64, BB / 64), 256>>>(
        BB, EE, 1024, emb, EE, feed, W_ic, 1024, nullptr, b_ic, px);

    // 2) gates = [x|h0] @ [W_ih|W_hh]^T + b_ih  (128 x 2048, K=1024)
    sgemm_cat<64, 64, 16, 4, 4><<<dim3(4 * HH / 64, BB / 64), 256>>>(
        BB, 4 * HH, 1024, px, EE, hidden, W_ih, EE, W_hh, b_ih, pgates);

    // 3) LSTM elementwise
    lstm_elem<<<(BB * HH + 255) / 256, 256>>>(pgates, b_hh, ctx0, ph1, pc1,
                                              out_h1, out_c1);

    // 4) dec_fea = h1 @ W_dec^T + b_att         (128 x 512, K=512)
    sgemm_cat<64, 64, 16, 4, 4><<<dim3(HH / 64, BB / 64), 256>>>(
        BB, HH, HH, ph1, HH, nullptr, W_dec, HH, nullptr, b_att, pdecfea);

    // 5) attention energies
    attn_e_kernel<<<(BB * SS) / 8, 256>>>(sfeat, pdecfea, cov, mask, v_att, w_c, pe);

    // 6) softmax over S + coverage update
    softmax_s_kernel<<<BB, 512>>>(pe, mask, cov, pattn, out_attn, out_cov);

    // 7) context vector
    ctx_kernel<<<dim3(BB, 2), 256>>>(pattn, states, pctx);

    // 8) dec_out = [h1|ctx] @ W_out^T + b_out   (128 x 512, K=1024)
    sgemm_cat<64, 64, 16, 4, 4><<<dim3(HH / 64, BB / 64), 256>>>(
        BB, HH, 1024, ph1, HH, pctx, W_out, 1024, nullptr, b_out, pdecout);

    // 9) p_gen + dec_out output copy
    pgen_kernel<<<BB, 128>>>(pdecout, W_pg, b_pg, ppgen, out_pgen, out_dec);

    // 10) vocab logits = dec_out @ W_v^T + b_v  (128 x 50257, K=512)
    sgemm_cat<128, 128, 16, 8, 8><<<dim3((VV + 127) / 128, 1), 256>>>(
        BB, VV, HH, pdecout, HH, nullptr, W_v, HH, nullptr, b_v, plogits);

    // 11) vocab softmax stats
    vocab_stats_kernel<<<BB, 512>>>(plogits, prowm, prows);

    // 12) final vocab distribution (incl. zero OOV tail)
    {
        long total = (long)BB * VEXTN;
        final_vocab_kernel<<<(int)((total + 255) / 256), 256>>>(
            plogits, prowm, prows, ppgen, out_final);
    }

    // 13) copy scatter
    scatter_kernel<<<(BB * SS + 255) / 256, 256>>>(srcids, pattn, ppgen, out_final);
}

// round 2
// speedup vs baseline: 3.8256x; 3.8256x over previous
#include <cuda_runtime.h>
#include <math.h>
#include <stdint.h>

// Problem constants
#define BB   128
#define SS   400
#define EE   512
#define HH   512
#define VV   50257
#define NOOV 50
#define VEXTN (VV + NOOV)   // 50307

// ---------------------------------------------------------------------------
// Scratch (device globals: allocation-free per harness rules)
// ---------------------------------------------------------------------------
__device__ float g_x[BB * EE];
__device__ float g_gates[BB * 4 * HH];
__device__ float g_h1[BB * HH];
__device__ float g_c1[BB * HH];
__device__ float g_decfea[BB * HH];
__device__ float g_ctx[BB * HH];
__device__ float g_decout[BB * HH];
__device__ float g_e[BB * SS];
__device__ float g_attn[BB * SS];
__device__ float g_pgen[BB];
__device__ float g_rowm[BB];
__device__ float g_rows[BB];
__device__ float g_logits[(size_t)BB * VV];   // 25.7 MB

__device__ __forceinline__ float sigmoidf_(float x) {
    return 1.f / (1.f + expf(-x));
}
__device__ __forceinline__ float tanh_approx(float x) {
    float y;
    asm("tanh.approx.f32 %0, %1;" : "=f"(y) : "f"(x));
    return y;
}

// ---------------------------------------------------------------------------
// Bias broadcast fill: C[m,n] = bias[n]
// ---------------------------------------------------------------------------
__global__ void fill_bias(float* __restrict__ C, const float* __restrict__ bias,
                          int N, int total)
{
    int idx = blockIdx.x * blockDim.x + threadIdx.x;
    if (idx < total) C[idx] = bias[idx % N];
}

// ---------------------------------------------------------------------------
// Split-K SGEMM for the small GEMMs.
// C[M,N] += Acat[M,K] * Bcat[N,K]^T, accumulated via atomicAdd.
// Acat[m,k] = (k<KA0) ? A0[m*KA0+k] : A1[m*(K-KA0)+(k-KA0)]; Bcat analogous.
// BM=64, BN=64, BK=32, 256 threads, 4x4 microtile. Requires M%64==0, N%64==0,
// K%(32*SPLIT)==0... (chunk = K/SPLIT must be multiple of 32), KA0%4==0, KB0%4==0.
// ---------------------------------------------------------------------------
template <int SPLIT>
__global__ __launch_bounds__(256) void sgemm_splitk(
    int M, int N, int K,
    const float* __restrict__ A0, int KA0, const float* __restrict__ A1,
    const float* __restrict__ B0, int KB0, const float* __restrict__ B1,
    float* __restrict__ C)
{
    constexpr int BM = 64, BN = 64, BK = 32;
    __shared__ float As[BK][BM + 4];
    __shared__ float Bs[BK][BN + 4];

    const int tid  = threadIdx.x;
    const int m0   = blockIdx.y * BM;
    const int n0   = blockIdx.x * BN;
    const int kchunk = K / SPLIT;
    const int kbeg = blockIdx.z * kchunk;
    const int trow = tid / 16;
    const int tcol = tid % 16;
    const int KA1  = K - KA0;
    const int KB1  = K - KB0;

    float acc[4][4];
#pragma unroll
    for (int i = 0; i < 4; i++)
#pragma unroll
        for (int j = 0; j < 4; j++) acc[i][j] = 0.f;

    for (int k0 = kbeg; k0 < kbeg + kchunk; k0 += BK) {
        // A tile: 64 rows x 32 k = 512 float4 slots, 2 per thread
#pragma unroll
        for (int r = 0; r < 2; r++) {
            int slot = tid + r * 256;
            int m = slot / 8;
            int kq = slot % 8;
            int k = k0 + kq * 4;
            int gm = m0 + m;
            float4 v;
            if (k < KA0) v = *(const float4*)(A0 + (size_t)gm * KA0 + k);
            else         v = *(const float4*)(A1 + (size_t)gm * KA1 + (k - KA0));
            As[kq * 4 + 0][m] = v.x; As[kq * 4 + 1][m] = v.y;
            As[kq * 4 + 2][m] = v.z; As[kq * 4 + 3][m] = v.w;
        }
        // B tile
#pragma unroll
        for (int r = 0; r < 2; r++) {
            int slot = tid + r * 256;
            int n = slot / 8;
            int kq = slot % 8;
            int k = k0 + kq * 4;
            int gn = n0 + n;
            float4 v;
            if (k < KB0) v = *(const float4*)(B0 + (size_t)gn * KB0 + k);
            else         v = *(const float4*)(B1 + (size_t)gn * KB1 + (k - KB0));
            Bs[kq * 4 + 0][n] = v.x; Bs[kq * 4 + 1][n] = v.y;
            Bs[kq * 4 + 2][n] = v.z; Bs[kq * 4 + 3][n] = v.w;
        }
        __syncthreads();

#pragma unroll
        for (int kk = 0; kk < BK; kk++) {
            float4 a = *(const float4*)&As[kk][trow * 4];
            float4 b = *(const float4*)&Bs[kk][tcol * 4];
            float av[4] = {a.x, a.y, a.z, a.w};
            float bv[4] = {b.x, b.y, b.z, b.w};
#pragma unroll
            for (int i = 0; i < 4; i++)
#pragma unroll
                for (int j = 0; j < 4; j++) acc[i][j] += av[i] * bv[j];
        }
        __syncthreads();
    }

#pragma unroll
    for (int i = 0; i < 4; i++) {
        int gm = m0 + trow * 4 + i;
#pragma unroll
        for (int j = 0; j < 4; j++) {
            int gn = n0 + tcol * 4 + j;
            atomicAdd(&C[(size_t)gm * N + gn], acc[i][j]);
        }
    }
}

// ---------------------------------------------------------------------------
// Vocab GEMM: C[128, VV] = A[128,512] * B[VV,512]^T + bias
// BM=128, BN=128, BK=16, 256 threads, 8x8 microtile, fully vectorized.
// ---------------------------------------------------------------------------
__global__ __launch_bounds__(256) void vocab_gemm(
    const float* __restrict__ A,
    const float* __restrict__ B,
    const float* __restrict__ bias,
    float* __restrict__ C)
{
    __shared__ float As[16][128 + 4];
    __shared__ float Bs[16][128 + 4];
    const int tid = threadIdx.x;
    const int n0 = blockIdx.x * 128;
    const int tcol = tid % 16;
    const int trow = tid / 16;

    float acc[8][8];
#pragma unroll
    for (int i = 0; i < 8; i++)
#pragma unroll
        for (int j = 0; j < 8; j++) acc[i][j] = 0.f;

    for (int k0 = 0; k0 < 512; k0 += 16) {
        // A tile: 128 rows x 16 k = 512 float4 slots
#pragma unroll
        for (int r = 0; r < 2; r++) {
            int slot = tid + r * 256;
            int m = slot / 4;
            int kq = slot % 4;
            float4 v = *(const float4*)(A + (size_t)m * 512 + k0 + kq * 4);
            As[kq * 4 + 0][m] = v.x; As[kq * 4 + 1][m] = v.y;
            As[kq * 4 + 2][m] = v.z; As[kq * 4 + 3][m] = v.w;
        }
        // B tile (guard n)
#pragma unroll
        for (int r = 0; r < 2; r++) {
            int slot = tid + r * 256;
            int n = slot / 4;
            int kq = slot % 4;
            int gn = n0 + n;
            float4 v = make_float4(0.f, 0.f, 0.f, 0.f);
            if (gn < VV) v = *(const float4*)(B + (size_t)gn * 512 + k0 + kq * 4);
            Bs[kq * 4 + 0][n] = v.x; Bs[kq * 4 + 1][n] = v.y;
            Bs[kq * 4 + 2][n] = v.z; Bs[kq * 4 + 3][n] = v.w;
        }
        __syncthreads();

#pragma unroll
        for (int kk = 0; kk < 16; kk++) {
            float a[8], b[8];
            *(float4*)&a[0] = *(const float4*)&As[kk][trow * 8];
            *(float4*)&a[4] = *(const float4*)&As[kk][trow * 8 + 4];
            *(float4*)&b[0] = *(const float4*)&Bs[kk][tcol * 8];
            *(float4*)&b[4] = *(const float4*)&Bs[kk][tcol * 8 + 4];
#pragma unroll
            for (int i = 0; i < 8; i++)
#pragma unroll
                for (int j = 0; j < 8; j++) acc[i][j] += a[i] * b[j];
        }
        __syncthreads();
    }

#pragma unroll
    for (int i = 0; i < 8; i++) {
        int gm = trow * 8 + i;
#pragma unroll
        for (int j = 0; j < 8; j++) {
            int gn = n0 + tcol * 8 + j;
            if (gn < VV)
                C[(size_t)gm * VV + gn] = acc[i][j] + bias[gn];
        }
    }
}

// ---------------------------------------------------------------------------
// LSTM elementwise
// ---------------------------------------------------------------------------
__global__ void lstm_elem(const float* __restrict__ gates,
                          const float* __restrict__ b_hh,
                          const float* __restrict__ c0,
                          float* __restrict__ h1, float* __restrict__ c1,
                          float* __restrict__ out_h1, float* __restrict__ out_c1)
{
    int idx = blockIdx.x * blockDim.x + threadIdx.x;
    if (idx >= BB * HH) return;
    int b = idx / HH, j = idx % HH;
    const float* g = gates + (size_t)b * 4 * HH;
    float iv = sigmoidf_(g[j]          + b_hh[j]);
    float fv = sigmoidf_(g[HH + j]     + b_hh[HH + j]);
    float gv = tanhf(    g[2 * HH + j] + b_hh[2 * HH + j]);
    float ov = sigmoidf_(g[3 * HH + j] + b_hh[3 * HH + j]);
    float c = fv * c0[idx] + iv * gv;
    float h = ov * tanhf(c);
    h1[idx] = h; c1[idx] = c;
    out_h1[idx] = h; out_c1[idx] = c;
}

// ---------------------------------------------------------------------------
// Attention energies (warp per (b,s) row), tanh.approx
// ---------------------------------------------------------------------------
__global__ void attn_e_kernel(const float* __restrict__ sf,
                              const float* __restrict__ dec_fea,
                              const float* __restrict__ cov,
                              const float* __restrict__ mask,
                              const float* __restrict__ v_att,
                              const float* __restrict__ w_c,
                              float* __restrict__ e)
{
    int gwarp = (blockIdx.x * blockDim.x + threadIdx.x) >> 5;
    int lane = threadIdx.x & 31;
    if (gwarp >= BB * SS) return;
    int b = gwarp / SS;
    float cadd = w_c[0] * cov[gwarp];

    const float4* row = (const float4*)(sf + (size_t)gwarp * HH);
    const float4* df  = (const float4*)(dec_fea + (size_t)b * HH);
    const float4* va  = (const float4*)(v_att);

    float acc = 0.f;
#pragma unroll
    for (int i = 0; i < HH / 128; i++) {
        float4 x = row[i * 32 + lane];
        float4 d = df[i * 32 + lane];
        float4 v = va[i * 32 + lane];
        acc += tanh_approx(x.x + d.x + cadd) * v.x;
        acc += tanh_approx(x.y + d.y + cadd) * v.y;
        acc += tanh_approx(x.z + d.z + cadd) * v.z;
        acc += tanh_approx(x.w + d.w + cadd) * v.w;
    }
#pragma unroll
    for (int off = 16; off; off >>= 1) acc += __shfl_xor_sync(0xffffffffu, acc, off);
    if (lane == 0) e[gwarp] = (mask[gwarp] > 0.f) ? acc : -1.0e9f;
}

// ---------------------------------------------------------------------------
// Softmax over S + mask renorm + coverage update
// ---------------------------------------------------------------------------
__global__ void softmax_s_kernel(const float* __restrict__ e,
                                 const float* __restrict__ mask,
                                 const float* __restrict__ cov,
                                 float* __restrict__ attn,
                                 float* __restrict__ out_attn,
                                 float* __restrict__ out_cov)
{
    int b = blockIdx.x;
    int tid = threadIdx.x;           // 512 threads
    __shared__ float sh[SS];
    __shared__ float r1[512];
    __shared__ float r2[512];

    float m = -3.0e38f;
    for (int s = tid; s < SS; s += 512) m = fmaxf(m, e[b * SS + s]);
    r1[tid] = m; __syncthreads();
    for (int off = 256; off; off >>= 1) {
        if (tid < off) r1[tid] = fmaxf(r1[tid], r1[tid + off]);
        __syncthreads();
    }
    m = r1[0];
    __syncthreads();

    float P = 0.f, Q = 0.f;
    for (int s = tid; s < SS; s += 512) {
        float p = __expf(e[b * SS + s] - m);
        sh[s] = p;
        P += p;
        Q += p * mask[b * SS + s];
    }
    r1[tid] = P; r2[tid] = Q; __syncthreads();
    for (int off = 256; off; off >>= 1) {
        if (tid < off) { r1[tid] += r1[tid + off]; r2[tid] += r2[tid + off]; }
        __syncthreads();
    }
    P = r1[0]; Q = r2[0];
    float denom = Q / P + 1e-12f;

    for (int s = tid; s < SS; s += 512) {
        float a = sh[s] * mask[b * SS + s] / P / denom;
        attn[b * SS + s] = a;
        out_attn[b * SS + s] = a;
        out_cov[b * SS + s] = cov[b * SS + s] + a;
    }
}

// ---------------------------------------------------------------------------
// Context: ctx[b,h] = sum_s attn[b,s] * states[b,s,h]
// ---------------------------------------------------------------------------
__global__ void ctx_kernel(const float* __restrict__ attn,
                           const float* __restrict__ states,
                           float* __restrict__ ctx)
{
    int b = blockIdx.x;
    int h = blockIdx.y * 256 + threadIdx.x;
    __shared__ float sa[SS];
    for (int s = threadIdx.x; s < SS; s += 256) sa[s] = attn[b * SS + s];
    __syncthreads();

    const float* st = states + (size_t)b * SS * HH + h;
    float a0 = 0.f, a1 = 0.f, a2 = 0.f, a3 = 0.f;
    for (int s = 0; s < SS; s += 4) {
        a0 += sa[s]     * st[(size_t)(s)     * HH];
        a1 += sa[s + 1] * st[(size_t)(s + 1) * HH];
        a2 += sa[s + 2] * st[(size_t)(s + 2) * HH];
        a3 += sa[s + 3] * st[(size_t)(s + 3) * HH];
    }
    ctx[b * HH + h] = (a0 + a1) + (a2 + a3);
}

// ---------------------------------------------------------------------------
// p_gen = sigmoid(dec_out . W_pg + b_pg); also copy dec_out to output
// ---------------------------------------------------------------------------
__global__ void pgen_kernel(const float* __restrict__ dec_out,
                            const float* __restrict__ W_pg,
                            const float* __restrict__ b_pg,
                            float* __restrict__ pgen,
                            float* __restrict__ out_pgen,
                            float* __restrict__ out_dec)
{
    int b = blockIdx.x;
    int tid = threadIdx.x;            // 128 threads
    float acc = 0.f;
    for (int j = tid; j < HH; j += 128) {
        float d = dec_out[b * HH + j];
        out_dec[b * HH + j] = d;
        acc += d * W_pg[j];
    }
    __shared__ float red[4];
#pragma unroll
    for (int off = 16; off; off >>= 1) acc += __shfl_xor_sync(0xffffffffu, acc, off);
    if ((tid & 31) == 0) red[tid >> 5] = acc;
    __syncthreads();
    if (tid == 0) {
        float t = red[0] + red[1] + red[2] + red[3];
        float p = sigmoidf_(t + b_pg[0]);
        pgen[b] = p;
        out_pgen[b] = p;
    }
}

// ---------------------------------------------------------------------------
// Row max + sum(exp) over vocab (online), one block per batch row
// ---------------------------------------------------------------------------
__global__ void vocab_stats_kernel(const float* __restrict__ logits,
                                   float* __restrict__ rowm,
                                   float* __restrict__ rows)
{
    int b = blockIdx.x;
    int tid = threadIdx.x;    // 512
    float m = -3.0e38f, s = 0.f;
    for (int v = tid; v < VV; v += 512) {
        float x = logits[(size_t)b * VV + v];
        if (x > m) {
            s = s * __expf(m - x) + 1.f;
            m = x;
        } else {
            s += __expf(x - m);
        }
    }
    __shared__ float sm[512], ssum[512];
    sm[tid] = m; ssum[tid] = s; __syncthreads();
    for (int off = 256; off; off >>= 1) {
        if (tid < off) {
            float m2 = sm[tid + off], s2 = ssum[tid + off];
            float M = fmaxf(sm[tid], m2);
            ssum[tid] = ssum[tid] * __expf(sm[tid] - M) + s2 * __expf(m2 - M);
            sm[tid] = M;
        }
        __syncthreads();
    }
    if (tid == 0) { rowm[b] = sm[0]; rows[b] = ssum[0]; }
}

// ---------------------------------------------------------------------------
// Final vocab distribution (p_gen * softmax, OOV zeros)
// ---------------------------------------------------------------------------
__global__ void final_vocab_kernel(const float* __restrict__ logits,
                                   const float* __restrict__ rowm,
                                   const float* __restrict__ rows,
                                   const float* __restrict__ pgen,
                                   float* __restrict__ outf)
{
    long idx = (long)blockIdx.x * blockDim.x + threadIdx.x;
    if (idx >= (long)BB * VEXTN) return;
    int b = (int)(idx / VEXTN);
    int n = (int)(idx % VEXTN);
    float val = 0.f;
    if (n < VV) {
        float scale = pgen[b] / rows[b];
        val = scale * __expf(logits[(size_t)b * VV + n] - rowm[b]);
    }
    outf[idx] = val;
}

// ---------------------------------------------------------------------------
// Copy-mechanism scatter
// ---------------------------------------------------------------------------
__global__ void scatter_kernel(const int* __restrict__ ids,
                               const float* __restrict__ attn,
                               const float* __restrict__ pgen,
                               float* __restrict__ outf)
{
    int idx = blockIdx.x * blockDim.x + threadIdx.x;
    if (idx >= BB * SS) return;
    int b = idx / SS;
    float v = (1.f - pgen[b]) * attn[idx];
    atomicAdd(&outf[(size_t)b * VEXTN + ids[idx]], v);
}

// ---------------------------------------------------------------------------
// Launcher
// ---------------------------------------------------------------------------
extern "C" void kernel_launch(void* const* d_in, const int* in_sizes, int n_in,
                              void* d_out, int out_size)
{
    const float* emb    = (const float*)d_in[0];
    const float* feed   = (const float*)d_in[1];
    const float* hidden = (const float*)d_in[2];
    const float* ctx0   = (const float*)d_in[3];
    const float* states = (const float*)d_in[4];
    const float* sfeat  = (const float*)d_in[5];
    const float* mask   = (const float*)d_in[6];
    const float* cov    = (const float*)d_in[7];
    const int*   srcids = (const int*)d_in[8];
    const float* W_ic   = (const float*)d_in[9];
    const float* b_ic   = (const float*)d_in[10];
    const float* W_ih   = (const float*)d_in[11];
    const float* W_hh   = (const float*)d_in[12];
    const float* b_ih   = (const float*)d_in[13];
    const float* b_hh   = (const float*)d_in[14];
    const float* W_dec  = (const float*)d_in[15];
    const float* b_att  = (const float*)d_in[16];
    const float* v_att  = (const float*)d_in[17];
    const float* w_c    = (const float*)d_in[18];
    const float* W_out  = (const float*)d_in[19];
    const float* b_out  = (const float*)d_in[20];
    const float* W_pg   = (const float*)d_in[21];
    const float* b_pg   = (const float*)d_in[22];
    const float* W_v    = (const float*)d_in[23];
    const float* b_v    = (const float*)d_in[24];

    float* out = (float*)d_out;
    float* out_final = out;
    float* out_pgen  = out_final + (size_t)BB * VEXTN;
    float* out_attn  = out_pgen + BB;
    float* out_cov   = out_attn + (size_t)BB * SS;
    float* out_h1    = out_cov + (size_t)BB * SS;
    float* out_c1    = out_h1 + (size_t)BB * HH;
    float* out_dec   = out_c1 + (size_t)BB * HH;

    float *px, *pgates, *ph1, *pc1, *pdecfea, *pctx, *pdecout;
    float *pe, *pattn, *ppgen, *prowm, *prows, *plogits;
    cudaGetSymbolAddress((void**)&px,      g_x);
    cudaGetSymbolAddress((void**)&pgates,  g_gates);
    cudaGetSymbolAddress((void**)&ph1,     g_h1);
    cudaGetSymbolAddress((void**)&pc1,     g_c1);
    cudaGetSymbolAddress((void**)&pdecfea, g_decfea);
    cudaGetSymbolAddress((void**)&pctx,    g_ctx);
    cudaGetSymbolAddress((void**)&pdecout, g_decout);
    cudaGetSymbolAddress((void**)&pe,      g_e);
    cudaGetSymbolAddress((void**)&pattn,   g_attn);
    cudaGetSymbolAddress((void**)&ppgen,   g_pgen);
    cudaGetSymbolAddress((void**)&prowm,   g_rowm);
    cudaGetSymbolAddress((void**)&prows,   g_rows);
    cudaGetSymbolAddress((void**)&plogits, g_logits);

    // 1) x = [emb|feed] @ W_ic^T + b_ic   (128 x 512, K=1024), split-K=8
    fill_bias<<<(BB * EE + 255) / 256, 256>>>(px, b_ic, EE, BB * EE);
    sgemm_splitk<8><<<dim3(EE / 64, BB / 64, 8), 256>>>(
        BB, EE, 1024, emb, EE, feed, W_ic, 1024, nullptr, px);

    // 2) gates = [x|h0] @ [W_ih|W_hh]^T + b_ih   (128 x 2048, K=1024), split-K=4
    fill_bias<<<(BB * 4 * HH + 255) / 256, 256>>>(pgates, b_ih, 4 * HH, BB * 4 * HH);
    sgemm_splitk<4><<<dim3(4 * HH / 64, BB / 64, 4), 256>>>(
        BB, 4 * HH, 1024, px, EE, hidden, W_ih, EE, W_hh, pgates);

    // 3) LSTM elementwise
    lstm_elem<<<(BB * HH + 255) / 256, 256>>>(pgates, b_hh, ctx0, ph1, pc1,
                                              out_h1, out_c1);

    // 4) dec_fea = h1 @ W_dec^T + b_att   (128 x 512, K=512), split-K=8
    fill_bias<<<(BB * HH + 255) / 256, 256>>>(pdecfea, b_att, HH, BB * HH);
    sgemm_splitk<8><<<dim3(HH / 64, BB / 64, 8), 256>>>(
        BB, HH, HH, ph1, HH, nullptr, W_dec, HH, nullptr, pdecfea);

    // 5) attention energies
    attn_e_kernel<<<(BB * SS) / 8, 256>>>(sfeat, pdecfea, cov, mask, v_att, w_c, pe);

    // 6) softmax over S + coverage update
    softmax_s_kernel<<<BB, 512>>>(pe, mask, cov, pattn, out_attn, out_cov);

    // 7) context vector
    ctx_kernel<<<dim3(BB, 2), 256>>>(pattn, states, pctx);

    // 8) dec_out = [h1|ctx] @ W_out^T + b_out   (128 x 512, K=1024), split-K=8
    fill_bias<<<(BB * HH + 255) / 256, 256>>>(pdecout, b_out, HH, BB * HH);
    sgemm_splitk<8><<<dim3(HH / 64, BB / 64, 8), 256>>>(
        BB, HH, 1024, ph1, HH, pctx, W_out, 1024, nullptr, pdecout);

    // 9) p_gen + dec_out output copy
    pgen_kernel<<<BB, 128>>>(pdecout, W_pg, b_pg, ppgen, out_pgen, out_dec);

    // 10) vocab logits = dec_out @ W_v^T + b_v   (128 x 50257, K=512)
    vocab_gemm<<<(VV + 127) / 128, 256>>>(pdecout, W_v, b_v, plogits);

    // 11) vocab softmax stats
    vocab_stats_kernel<<<BB, 512>>>(plogits, prowm, prows);

    // 12) final vocab distribution (incl. zero OOV tail)
    {
        long total = (long)BB * VEXTN;
        final_vocab_kernel<<<(int)((total + 255) / 256), 256>>>(
            plogits, prowm, prows, ppgen, out_final);
    }

    // 13) copy scatter
    scatter_kernel<<<(BB * SS + 255) / 256, 256>>>(srcids, pattn, ppgen, out_final);
}

// round 3
// speedup vs baseline: 6.1972x; 1.6200x over previous
#include <cuda_runtime.h>
#include <cuda_bf16.h>
#include <math.h>
#include <stdint.h>

// Problem constants
#define BB   128
#define SS   400
#define EE   512
#define HH   512
#define VV   50257
#define NOOV 50
#define VEXTN (VV + NOOV)   // 50307

// ---------------------------------------------------------------------------
// Scratch (device globals: allocation-free per harness rules)
// ---------------------------------------------------------------------------
__device__ float g_x[BB * EE];
__device__ float g_gates[BB * 4 * HH];
__device__ float g_h1[BB * HH];
__device__ float g_c1[BB * HH];
__device__ float g_decfea[BB * HH];
__device__ float g_ctx[BB * HH];
__device__ float g_decout[BB * HH];
__device__ __nv_bfloat16 g_dec_bf[BB * HH];
__device__ float g_e[BB * SS];
__device__ float g_attn[BB * SS];
__device__ float g_pgen[BB];
__device__ float g_rowm[BB];
__device__ float g_rows[BB];
__device__ float g_logits[(size_t)BB * VV];   // 25.7 MB

__device__ __forceinline__ float sigmoidf_(float x) {
    return 1.f / (1.f + expf(-x));
}
__device__ __forceinline__ float tanh_approx(float x) {
    float y;
    asm("tanh.approx.f32 %0, %1;" : "=f"(y) : "f"(x));
    return y;
}

// ---------------------------------------------------------------------------
// Bias broadcast fill: C[m,n] = bias[n]
// ---------------------------------------------------------------------------
__global__ void fill_bias(float* __restrict__ C, const float* __restrict__ bias,
                          int N, int total)
{
    int idx = blockIdx.x * blockDim.x + threadIdx.x;
    if (idx < total) C[idx] = bias[idx % N];
}

// ---------------------------------------------------------------------------
// Split-K SGEMM for the small GEMMs (fp32, atomic accumulate).
// ---------------------------------------------------------------------------
template <int SPLIT>
__global__ __launch_bounds__(256) void sgemm_splitk(
    int M, int N, int K,
    const float* __restrict__ A0, int KA0, const float* __restrict__ A1,
    const float* __restrict__ B0, int KB0, const float* __restrict__ B1,
    float* __restrict__ C)
{
    constexpr int BM = 64, BN = 64, BK = 32;
    __shared__ float As[BK][BM + 4];
    __shared__ float Bs[BK][BN + 4];

    const int tid  = threadIdx.x;
    const int m0   = blockIdx.y * BM;
    const int n0   = blockIdx.x * BN;
    const int kchunk = K / SPLIT;
    const int kbeg = blockIdx.z * kchunk;
    const int trow = tid / 16;
    const int tcol = tid % 16;
    const int KA1  = K - KA0;
    const int KB1  = K - KB0;

    float acc[4][4];
#pragma unroll
    for (int i = 0; i < 4; i++)
#pragma unroll
        for (int j = 0; j < 4; j++) acc[i][j] = 0.f;

    for (int k0 = kbeg; k0 < kbeg + kchunk; k0 += BK) {
#pragma unroll
        for (int r = 0; r < 2; r++) {
            int slot = tid + r * 256;
            int m = slot / 8;
            int kq = slot % 8;
            int k = k0 + kq * 4;
            int gm = m0 + m;
            float4 v;
            if (k < KA0) v = *(const float4*)(A0 + (size_t)gm * KA0 + k);
            else         v = *(const float4*)(A1 + (size_t)gm * KA1 + (k - KA0));
            As[kq * 4 + 0][m] = v.x; As[kq * 4 + 1][m] = v.y;
            As[kq * 4 + 2][m] = v.z; As[kq * 4 + 3][m] = v.w;
        }
#pragma unroll
        for (int r = 0; r < 2; r++) {
            int slot = tid + r * 256;
            int n = slot / 8;
            int kq = slot % 8;
            int k = k0 + kq * 4;
            int gn = n0 + n;
            float4 v;
            if (k < KB0) v = *(const float4*)(B0 + (size_t)gn * KB0 + k);
            else         v = *(const float4*)(B1 + (size_t)gn * KB1 + (k - KB0));
            Bs[kq * 4 + 0][n] = v.x; Bs[kq * 4 + 1][n] = v.y;
            Bs[kq * 4 + 2][n] = v.z; Bs[kq * 4 + 3][n] = v.w;
        }
        __syncthreads();

#pragma unroll
        for (int kk = 0; kk < BK; kk++) {
            float4 a = *(const float4*)&As[kk][trow * 4];
            float4 b = *(const float4*)&Bs[kk][tcol * 4];
            float av[4] = {a.x, a.y, a.z, a.w};
            float bv[4] = {b.x, b.y, b.z, b.w};
#pragma unroll
            for (int i = 0; i < 4; i++)
#pragma unroll
                for (int j = 0; j < 4; j++) acc[i][j] += av[i] * bv[j];
        }
        __syncthreads();
    }

#pragma unroll
    for (int i = 0; i < 4; i++) {
        int gm = m0 + trow * 4 + i;
#pragma unroll
        for (int j = 0; j < 4; j++) {
            int gn = n0 + tcol * 4 + j;
            atomicAdd(&C[(size_t)gm * N + gn], acc[i][j]);
        }
    }
}

// ---------------------------------------------------------------------------
// Vocab GEMM via bf16 tensor cores:
// C[128, VV] = A[128,512] * B[VV,512]^T + bias
// A pre-converted to bf16 (g_dec_bf). B (W_v) loaded fp32, converted in-flight.
// Block: 128 x 128 tile, BK=32 stage, 256 threads = 8 warps (4m x 2n),
// warp tile 32x64 via mma.sync m16n8k16.
// ---------------------------------------------------------------------------
#define VPITCH 40   // smem row pitch in bf16 elems (conflict-free LDSM)

__global__ __launch_bounds__(256) void vocab_gemm_mma(
    const __nv_bfloat16* __restrict__ Abf,   // [128][512]
    const float* __restrict__ B,             // [VV][512]
    const float* __restrict__ bias,
    float* __restrict__ C)
{
    __shared__ __nv_bfloat16 As[128 * VPITCH];
    __shared__ __nv_bfloat16 Bs[128 * VPITCH];

    const int tid  = threadIdx.x;
    const int n0   = blockIdx.x * 128;
    const int wid  = tid >> 5;
    const int lane = tid & 31;
    const int warp_m = (wid & 3) * 32;   // 4 warps over m
    const int warp_n = (wid >> 2) * 64;  // 2 warps over n

    const uint32_t as_base = (uint32_t)__cvta_generic_to_shared(As);
    const uint32_t bs_base = (uint32_t)__cvta_generic_to_shared(Bs);

    float acc[2][8][4];
#pragma unroll
    for (int i = 0; i < 2; i++)
#pragma unroll
        for (int j = 0; j < 8; j++)
#pragma unroll
            for (int t = 0; t < 4; t++) acc[i][j][t] = 0.f;

    for (int k0 = 0; k0 < 512; k0 += 32) {
        // ---- stage A: 128 x 32 bf16, 2 x 16B per thread ----
#pragma unroll
        for (int r = 0; r < 2; r++) {
            int slot = tid + r * 256;        // 0..511
            int m  = slot >> 2;
            int kq = slot & 3;               // 8 halves each
            uint4 v = *(const uint4*)(Abf + (size_t)m * 512 + k0 + kq * 8);
            *(uint4*)(As + m * VPITCH + kq * 8) = v;
        }
        // ---- stage B: 128 x 32 fp32 -> bf16, 4 x float4 per thread ----
#pragma unroll
        for (int r = 0; r < 4; r++) {
            int slot = tid + r * 256;        // 0..1023
            int n  = slot >> 3;
            int c4 = slot & 7;               // which float4 (4 k-values)
            int gn = n0 + n;
            float4 v = make_float4(0.f, 0.f, 0.f, 0.f);
            if (gn < VV)
                v = *(const float4*)(B + (size_t)gn * 512 + k0 + c4 * 4);
            __nv_bfloat162* dst = (__nv_bfloat162*)(Bs + n * VPITCH + c4 * 4);
            dst[0] = __floats2bfloat162_rn(v.x, v.y);
            dst[1] = __floats2bfloat162_rn(v.z, v.w);
        }
        __syncthreads();

#pragma unroll
        for (int kk = 0; kk < 2; kk++) {
            const int kb = kk * 16;
            // A fragments: 2 x ldmatrix.x4 (16x16 each)
            uint32_t a[2][4];
#pragma unroll
            for (int mi = 0; mi < 2; mi++) {
                int row = warp_m + mi * 16 + (lane & 15);
                int col = kb + (lane >> 4) * 8;
                uint32_t addr = as_base + (row * VPITCH + col) * 2;
                asm volatile(
                    "ldmatrix.sync.aligned.m8n8.x4.shared.b16 {%0,%1,%2,%3}, [%4];"
                    : "=r"(a[mi][0]), "=r"(a[mi][1]), "=r"(a[mi][2]), "=r"(a[mi][3])
                    : "r"(addr));
            }
            // B fragments: 4 x ldmatrix.x4, each covers two n8 tiles
            uint32_t b[8][2];
#pragma unroll
            for (int nq = 0; nq < 4; nq++) {
                int g = lane >> 3;
                int within = lane & 7;
                int row_n = warp_n + nq * 16 + within + (g >> 1) * 8;
                int colk = kb + (g & 1) * 8;
                uint32_t addr = bs_base + (row_n * VPITCH + colk) * 2;
                uint32_t r0, r1, r2, r3;
                asm volatile(
                    "ldmatrix.sync.aligned.m8n8.x4.shared.b16 {%0,%1,%2,%3}, [%4];"
                    : "=r"(r0), "=r"(r1), "=r"(r2), "=r"(r3)
                    : "r"(addr));
                b[nq * 2 + 0][0] = r0; b[nq * 2 + 0][1] = r1;
                b[nq * 2 + 1][0] = r2; b[nq * 2 + 1][1] = r3;
            }
            // MMA
#pragma unroll
            for (int mi = 0; mi < 2; mi++)
#pragma unroll
                for (int nj = 0; nj < 8; nj++) {
                    asm volatile(
                        "mma.sync.aligned.m16n8k16.row.col.f32.bf16.bf16.f32 "
                        "{%0,%1,%2,%3}, {%4,%5,%6,%7}, {%8,%9}, {%0,%1,%2,%3};"
                        : "+f"(acc[mi][nj][0]), "+f"(acc[mi][nj][1]),
                          "+f"(acc[mi][nj][2]), "+f"(acc[mi][nj][3])
                        : "r"(a[mi][0]), "r"(a[mi][1]), "r"(a[mi][2]), "r"(a[mi][3]),
                          "r"(b[nj][0]), "r"(b[nj][1]));
                }
        }
        __syncthreads();
    }

    // ---- epilogue: bias + store fp32 ----
#pragma unroll
    for (int mi = 0; mi < 2; mi++) {
        int m = warp_m + mi * 16 + (lane >> 2);
#pragma unroll
        for (int nj = 0; nj < 8; nj++) {
            int n = n0 + warp_n + nj * 8 + (lane & 3) * 2;
            if (n < VV)     C[(size_t)m * VV + n]     = acc[mi][nj][0] + bias[n];
            if (n + 1 < VV) C[(size_t)m * VV + n + 1] = acc[mi][nj][1] + bias[n + 1];
            int m2 = m + 8;
            if (n < VV)     C[(size_t)m2 * VV + n]     = acc[mi][nj][2] + bias[n];
            if (n + 1 < VV) C[(size_t)m2 * VV + n + 1] = acc[mi][nj][3] + bias[n + 1];
        }
    }
}

// ---------------------------------------------------------------------------
// Convert dec_out fp32 -> bf16
// ---------------------------------------------------------------------------
__global__ void cvt_dec_bf16(const float* __restrict__ src,
                             __nv_bfloat16* __restrict__ dst)
{
    int idx = blockIdx.x * blockDim.x + threadIdx.x;
    if (idx < BB * HH) dst[idx] = __float2bfloat16_rn(src[idx]);
}

// ---------------------------------------------------------------------------
// LSTM elementwise
// ---------------------------------------------------------------------------
__global__ void lstm_elem(const float* __restrict__ gates,
                          const float* __restrict__ b_hh,
                          const float* __restrict__ c0,
                          float* __restrict__ h1, float* __restrict__ c1,
                          float* __restrict__ out_h1, float* __restrict__ out_c1)
{
    int idx = blockIdx.x * blockDim.x + threadIdx.x;
    if (idx >= BB * HH) return;
    int b = idx / HH, j = idx % HH;
    const float* g = gates + (size_t)b * 4 * HH;
    float iv = sigmoidf_(g[j]          + b_hh[j]);
    float fv = sigmoidf_(g[HH + j]     + b_hh[HH + j]);
    float gv = tanhf(    g[2 * HH + j] + b_hh[2 * HH + j]);
    float ov = sigmoidf_(g[3 * HH + j] + b_hh[3 * HH + j]);
    float c = fv * c0[idx] + iv * gv;
    float h = ov * tanhf(c);
    h1[idx] = h; c1[idx] = c;
    out_h1[idx] = h; out_c1[idx] = c;
}

// ---------------------------------------------------------------------------
// Attention energies (warp per (b,s) row), tanh.approx
// ---------------------------------------------------------------------------
__global__ void attn_e_kernel(const float* __restrict__ sf,
                              const float* __restrict__ dec_fea,
                              const float* __restrict__ cov,
                              const float* __restrict__ mask,
                              const float* __restrict__ v_att,
                              const float* __restrict__ w_c,
                              float* __restrict__ e)
{
    int gwarp = (blockIdx.x * blockDim.x + threadIdx.x) >> 5;
    int lane = threadIdx.x & 31;
    if (gwarp >= BB * SS) return;
    int b = gwarp / SS;
    float cadd = w_c[0] * cov[gwarp];

    const float4* row = (const float4*)(sf + (size_t)gwarp * HH);
    const float4* df  = (const float4*)(dec_fea + (size_t)b * HH);
    const float4* va  = (const float4*)(v_att);

    float acc = 0.f;
#pragma unroll
    for (int i = 0; i < HH / 128; i++) {
        float4 x = row[i * 32 + lane];
        float4 d = df[i * 32 + lane];
        float4 v = va[i * 32 + lane];
        acc += tanh_approx(x.x + d.x + cadd) * v.x;
        acc += tanh_approx(x.y + d.y + cadd) * v.y;
        acc += tanh_approx(x.z + d.z + cadd) * v.z;
        acc += tanh_approx(x.w + d.w + cadd) * v.w;
    }
#pragma unroll
    for (int off = 16; off; off >>= 1) acc += __shfl_xor_sync(0xffffffffu, acc, off);
    if (lane == 0) e[gwarp] = (mask[gwarp] > 0.f) ? acc : -1.0e9f;
}

// ---------------------------------------------------------------------------
// Softmax over S + mask renorm + coverage update
// ---------------------------------------------------------------------------
__global__ void softmax_s_kernel(const float* __restrict__ e,
                                 const float* __restrict__ mask,
                                 const float* __restrict__ cov,
                                 float* __restrict__ attn,
                                 float* __restrict__ out_attn,
                                 float* __restrict__ out_cov)
{
    int b = blockIdx.x;
    int tid = threadIdx.x;           // 512 threads
    __shared__ float sh[SS];
    __shared__ float r1[512];
    __shared__ float r2[512];

    float m = -3.0e38f;
    for (int s = tid; s < SS; s += 512) m = fmaxf(m, e[b * SS + s]);
    r1[tid] = m; __syncthreads();
    for (int off = 256; off; off >>= 1) {
        if (tid < off) r1[tid] = fmaxf(r1[tid], r1[tid + off]);
        __syncthreads();
    }
    m = r1[0];
    __syncthreads();

    float P = 0.f, Q = 0.f;
    for (int s = tid; s < SS; s += 512) {
        float p = __expf(e[b * SS + s] - m);
        sh[s] = p;
        P += p;
        Q += p * mask[b * SS + s];
    }
    r1[tid] = P; r2[tid] = Q; __syncthreads();
    for (int off = 256; off; off >>= 1) {
        if (tid < off) { r1[tid] += r1[tid + off]; r2[tid] += r2[tid + off]; }
        __syncthreads();
    }
    P = r1[0]; Q = r2[0];
    float denom = Q / P + 1e-12f;

    for (int s = tid; s < SS; s += 512) {
        float a = sh[s] * mask[b * SS + s] / P / denom;
        attn[b * SS + s] = a;
        out_attn[b * SS + s] = a;
        out_cov[b * SS + s] = cov[b * SS + s] + a;
    }
}

// ---------------------------------------------------------------------------
// Context: ctx[b,h] = sum_s attn[b,s] * states[b,s,h]
// ---------------------------------------------------------------------------
__global__ void ctx_kernel(const float* __restrict__ attn,
                           const float* __restrict__ states,
                           float* __restrict__ ctx)
{
    int b = blockIdx.x;
    int h = blockIdx.y * 256 + threadIdx.x;
    __shared__ float sa[SS];
    for (int s = threadIdx.x; s < SS; s += 256) sa[s] = attn[b * SS + s];
    __syncthreads();

    const float* st = states + (size_t)b * SS * HH + h;
    float a0 = 0.f, a1 = 0.f, a2 = 0.f, a3 = 0.f;
    for (int s = 0; s < SS; s += 4) {
        a0 += sa[s]     * st[(size_t)(s)     * HH];
        a1 += sa[s + 1] * st[(size_t)(s + 1) * HH];
        a2 += sa[s + 2] * st[(size_t)(s + 2) * HH];
        a3 += sa[s + 3] * st[(size_t)(s + 3) * HH];
    }
    ctx[b * HH + h] = (a0 + a1) + (a2 + a3);
}

// ---------------------------------------------------------------------------
// p_gen = sigmoid(dec_out . W_pg + b_pg); also copy dec_out to output
// ---------------------------------------------------------------------------
__global__ void pgen_kernel(const float* __restrict__ dec_out,
                            const float* __restrict__ W_pg,
                            const float* __restrict__ b_pg,
                            float* __restrict__ pgen,
                            float* __restrict__ out_pgen,
                            float* __restrict__ out_dec)
{
    int b = blockIdx.x;
    int tid = threadIdx.x;            // 128 threads
    float acc = 0.f;
    for (int j = tid; j < HH; j += 128) {
        float d = dec_out[b * HH + j];
        out_dec[b * HH + j] = d;
        acc += d * W_pg[j];
    }
    __shared__ float red[4];
#pragma unroll
    for (int off = 16; off; off >>= 1) acc += __shfl_xor_sync(0xffffffffu, acc, off);
    if ((tid & 31) == 0) red[tid >> 5] = acc;
    __syncthreads();
    if (tid == 0) {
        float t = red[0] + red[1] + red[2] + red[3];
        float p = sigmoidf_(t + b_pg[0]);
        pgen[b] = p;
        out_pgen[b] = p;
    }
}

// ---------------------------------------------------------------------------
// Row max + sum(exp) over vocab (online), one block per batch row
// ---------------------------------------------------------------------------
__global__ void vocab_stats_kernel(const float* __restrict__ logits,
                                   float* __restrict__ rowm,
                                   float* __restrict__ rows)
{
    int b = blockIdx.x;
    int tid = threadIdx.x;    // 512
    float m = -3.0e38f, s = 0.f;
    for (int v = tid; v < VV; v += 512) {
        float x = logits[(size_t)b * VV + v];
        if (x > m) {
            s = s * __expf(m - x) + 1.f;
            m = x;
        } else {
            s += __expf(x - m);
        }
    }
    __shared__ float sm[512], ssum[512];
    sm[tid] = m; ssum[tid] = s; __syncthreads();
    for (int off = 256; off; off >>= 1) {
        if (tid < off) {
            float m2 = sm[tid + off], s2 = ssum[tid + off];
            float M = fmaxf(sm[tid], m2);
            ssum[tid] = ssum[tid] * __expf(sm[tid] - M) + s2 * __expf(m2 - M);
            sm[tid] = M;
        }
        __syncthreads();
    }
    if (tid == 0) { rowm[b] = sm[0]; rows[b] = ssum[0]; }
}

// ---------------------------------------------------------------------------
// Final vocab distribution (p_gen * softmax, OOV zeros)
// ---------------------------------------------------------------------------
__global__ void final_vocab_kernel(const float* __restrict__ logits,
                                   const float* __restrict__ rowm,
                                   const float* __restrict__ rows,
                                   const float* __restrict__ pgen,
                                   float* __restrict__ outf)
{
    long idx = (long)blockIdx.x * blockDim.x + threadIdx.x;
    if (idx >= (long)BB * VEXTN) return;
    int b = (int)(idx / VEXTN);
    int n = (int)(idx % VEXTN);
    float val = 0.f;
    if (n < VV) {
        float scale = pgen[b] / rows[b];
        val = scale * __expf(logits[(size_t)b * VV + n] - rowm[b]);
    }
    outf[idx] = val;
}

// ---------------------------------------------------------------------------
// Copy-mechanism scatter
// ---------------------------------------------------------------------------
__global__ void scatter_kernel(const int* __restrict__ ids,
                               const float* __restrict__ attn,
                               const float* __restrict__ pgen,
                               float* __restrict__ outf)
{
    int idx = blockIdx.x * blockDim.x + threadIdx.x;
    if (idx >= BB * SS) return;
    int b = idx / SS;
    float v = (1.f - pgen[b]) * attn[idx];
    atomicAdd(&outf[(size_t)b * VEXTN + ids[idx]], v);
}

// ---------------------------------------------------------------------------
// Launcher
// ---------------------------------------------------------------------------
extern "C" void kernel_launch(void* const* d_in, const int* in_sizes, int n_in,
                              void* d_out, int out_size)
{
    const float* emb    = (const float*)d_in[0];
    const float* feed   = (const float*)d_in[1];
    const float* hidden = (const float*)d_in[2];
    const float* ctx0   = (const float*)d_in[3];
    const float* states = (const float*)d_in[4];
    const float* sfeat  = (const float*)d_in[5];
    const float* mask   = (const float*)d_in[6];
    const float* cov    = (const float*)d_in[7];
    const int*   srcids = (const int*)d_in[8];
    const float* W_ic   = (const float*)d_in[9];
    const float* b_ic   = (const float*)d_in[10];
    const float* W_ih   = (const float*)d_in[11];
    const float* W_hh   = (const float*)d_in[12];
    const float* b_ih   = (const float*)d_in[13];
    const float* b_hh   = (const float*)d_in[14];
    const float* W_dec  = (const float*)d_in[15];
    const float* b_att  = (const float*)d_in[16];
    const float* v_att  = (const float*)d_in[17];
    const float* w_c    = (const float*)d_in[18];
    const float* W_out  = (const float*)d_in[19];
    const float* b_out  = (const float*)d_in[20];
    const float* W_pg   = (const float*)d_in[21];
    const float* b_pg   = (const float*)d_in[22];
    const float* W_v    = (const float*)d_in[23];
    const float* b_v    = (const float*)d_in[24];

    float* out = (float*)d_out;
    float* out_final = out;
    float* out_pgen  = out_final + (size_t)BB * VEXTN;
    float* out_attn  = out_pgen + BB;
    float* out_cov   = out_attn + (size_t)BB * SS;
    float* out_h1    = out_cov + (size_t)BB * SS;
    float* out_c1    = out_h1 + (size_t)BB * HH;
    float* out_dec   = out_c1 + (size_t)BB * HH;

    float *px, *pgates, *ph1, *pc1, *pdecfea, *pctx, *pdecout;
    float *pe, *pattn, *ppgen, *prowm, *prows, *plogits;
    __nv_bfloat16* pdecbf;
    cudaGetSymbolAddress((void**)&px,      g_x);
    cudaGetSymbolAddress((void**)&pgates,  g_gates);
    cudaGetSymbolAddress((void**)&ph1,     g_h1);
    cudaGetSymbolAddress((void**)&pc1,     g_c1);
    cudaGetSymbolAddress((void**)&pdecfea, g_decfea);
    cudaGetSymbolAddress((void**)&pctx,    g_ctx);
    cudaGetSymbolAddress((void**)&pdecout, g_decout);
    cudaGetSymbolAddress((void**)&pdecbf,  g_dec_bf);
    cudaGetSymbolAddress((void**)&pe,      g_e);
    cudaGetSymbolAddress((void**)&pattn,   g_attn);
    cudaGetSymbolAddress((void**)&ppgen,   g_pgen);
    cudaGetSymbolAddress((void**)&prowm,   g_rowm);
    cudaGetSymbolAddress((void**)&prows,   g_rows);
    cudaGetSymbolAddress((void**)&plogits, g_logits);

    // 1) x = [emb|feed] @ W_ic^T + b_ic   (128 x 512, K=1024), split-K=8
    fill_bias<<<(BB * EE + 255) / 256, 256>>>(px, b_ic, EE, BB * EE);
    sgemm_splitk<8><<<dim3(EE / 64, BB / 64, 8), 256>>>(
        BB, EE, 1024, emb, EE, feed, W_ic, 1024, nullptr, px);

    // 2) gates = [x|h0] @ [W_ih|W_hh]^T + b_ih   (128 x 2048, K=1024), split-K=4
    fill_bias<<<(BB * 4 * HH + 255) / 256, 256>>>(pgates, b_ih, 4 * HH, BB * 4 * HH);
    sgemm_splitk<4><<<dim3(4 * HH / 64, BB / 64, 4), 256>>>(
        BB, 4 * HH, 1024, px, EE, hidden, W_ih, EE, W_hh, pgates);

    // 3) LSTM elementwise
    lstm_elem<<<(BB * HH + 255) / 256, 256>>>(pgates, b_hh, ctx0, ph1, pc1,
                                              out_h1, out_c1);

    // 4) dec_fea = h1 @ W_dec^T + b_att   (128 x 512, K=512), split-K=8
    fill_bias<<<(BB * HH + 255) / 256, 256>>>(pdecfea, b_att, HH, BB * HH);
    sgemm_splitk<8><<<dim3(HH / 64, BB / 64, 8), 256>>>(
        BB, HH, HH, ph1, HH, nullptr, W_dec, HH, nullptr, pdecfea);

    // 5) attention energies
    attn_e_kernel<<<(BB * SS) / 8, 256>>>(sfeat, pdecfea, cov, mask, v_att, w_c, pe);

    // 6) softmax over S + coverage update
    softmax_s_kernel<<<BB, 512>>>(pe, mask, cov, pattn, out_attn, out_cov);

    // 7) context vector
    ctx_kernel<<<dim3(BB, 2), 256>>>(pattn, states, pctx);

    // 8) dec_out = [h1|ctx] @ W_out^T + b_out   (128 x 512, K=1024), split-K=8
    fill_bias<<<(BB * HH + 255) / 256, 256>>>(pdecout, b_out, HH, BB * HH);
    sgemm_splitk<8><<<dim3(HH / 64, BB / 64, 8), 256>>>(
        BB, HH, 1024, ph1, HH, pctx, W_out, 1024, nullptr, pdecout);

    // 9) p_gen + dec_out output copy
    pgen_kernel<<<BB, 128>>>(pdecout, W_pg, b_pg, ppgen, out_pgen, out_dec);

    // 9b) convert dec_out to bf16 for tensor-core GEMM
    cvt_dec_bf16<<<(BB * HH + 255) / 256, 256>>>(pdecout, pdecbf);

    // 10) vocab logits = dec_out @ W_v^T + b_v   (bf16 tensor cores)
    vocab_gemm_mma<<<(VV + 127) / 128, 256>>>(pdecbf, W_v, b_v, plogits);

    // 11) vocab softmax stats
    vocab_stats_kernel<<<BB, 512>>>(plogits, prowm, prows);

    // 12) final vocab distribution (incl. zero OOV tail)
    {
        long total = (long)BB * VEXTN;
        final_vocab_kernel<<<(int)((total + 255) / 256), 256>>>(
            plogits, prowm, prows, ppgen, out_final);
    }

    // 13) copy scatter
    scatter_kernel<<<(BB * SS + 255) / 256, 256>>>(srcids, pattn, ppgen, out_final);
}

// round 4
// speedup vs baseline: 7.4431x; 1.2010x over previous
#include <cuda_runtime.h>
#include <cuda_bf16.h>
#include <math.h>
#include <stdint.h>

// Problem constants
#define BB   128
#define SS   400
#define EE   512
#define HH   512
#define VV   50257
#define NOOV 50
#define VEXTN (VV + NOOV)   // 50307

// ---------------------------------------------------------------------------
// Scratch (device globals: allocation-free per harness rules)
// ---------------------------------------------------------------------------
__device__ float g_x[BB * EE];
__device__ float g_gates[BB * 4 * HH];
__device__ float g_h1[BB * HH];
__device__ float g_c1[BB * HH];
__device__ float g_decfea[BB * HH];
__device__ float g_ctx[BB * HH];
__device__ float g_decout[BB * HH];
__device__ __nv_bfloat16 g_dec_bf[BB * HH];
__device__ float g_e[BB * SS];
__device__ float g_attn[BB * SS];
__device__ float g_pgen[BB];
__device__ float g_rowm[BB];
__device__ float g_rows[BB];
__device__ float g_logits[(size_t)BB * VV];   // 25.7 MB

__device__ __forceinline__ float sigmoidf_(float x) {
    return 1.f / (1.f + expf(-x));
}
__device__ __forceinline__ float tanh_approx(float x) {
    float y;
    asm("tanh.approx.f32 %0, %1;" : "=f"(y) : "f"(x));
    return y;
}
__device__ __forceinline__ uint32_t f2tf32(float x) {
    uint32_t o;
    asm("cvt.rna.tf32.f32 %0, %1;" : "=r"(o) : "f"(x));
    return o;
}

// ---------------------------------------------------------------------------
// One fused bias-broadcast fill for the 4 GEMM outputs.
// segments: px[128*512] <- b_ic(512); pgates[128*2048] <- b_ih(2048);
//           pdecfea[128*512] <- b_att(512); pdecout[128*512] <- b_out(512)
// ---------------------------------------------------------------------------
__global__ void fill_bias_all(float* __restrict__ px, const float* __restrict__ b_ic,
                              float* __restrict__ pgates, const float* __restrict__ b_ih,
                              float* __restrict__ pdecfea, const float* __restrict__ b_att,
                              float* __restrict__ pdecout, const float* __restrict__ b_out)
{
    int i = blockIdx.x * blockDim.x + threadIdx.x;   // < 458752
    if (i < 65536) {
        px[i] = b_ic[i & 511];
    } else if (i < 327680) {
        int j = i - 65536;
        pgates[j] = b_ih[j & 2047];
    } else if (i < 393216) {
        int j = i - 327680;
        pdecfea[j] = b_att[j & 511];
    } else if (i < 458752) {
        int j = i - 393216;
        pdecout[j] = b_out[j & 511];
    }
}

// ---------------------------------------------------------------------------
// Small GEMM via tf32 tensor cores, split-K with fp32 atomic reduce.
// C[128, N] += Acat[128,K] * Bcat[N,K]^T
// Acat[m,k] = (k<KA0) ? A0 : A1; Bcat[n,k] = (k<KB0) ? B0 : B1.
// Block: 128(M) x 64(N) tile, BK=16 stages, 256 threads = 8 warps (4m x 2n).
// grid = (N/64, 1, K/kchunk). Requires K,kchunk % 16 == 0; KA0,KB0 % 4 == 0.
// ---------------------------------------------------------------------------
#define TP 20   // smem pitch in words (conflict-free for frag loads)

__global__ __launch_bounds__(256) void gemm_tf32_splitk(
    int N, int K, int kchunk,
    const float* __restrict__ A0, int KA0, const float* __restrict__ A1,
    const float* __restrict__ B0, int KB0, const float* __restrict__ B1,
    float* __restrict__ C)
{
    __shared__ uint32_t As[128 * TP];
    __shared__ uint32_t Bs[64 * TP];

    const int tid  = threadIdx.x;
    const int n0   = blockIdx.x * 64;
    const int kbeg = blockIdx.z * kchunk;
    const int kend = kbeg + kchunk;
    const int wid  = tid >> 5;
    const int lane = tid & 31;
    const int wm   = (wid & 3) * 32;
    const int wn   = (wid >> 2) * 32;
    const int r    = lane >> 2;
    const int c    = lane & 3;
    const int KA1  = K - KA0;
    const int KB1  = K - KB0;

    // per-thread staging indices
    const int am0 = (tid) >> 2,        akq0 = (tid) & 3;
    const int am1 = (tid + 256) >> 2,  akq1 = (tid + 256) & 3;
    const int bn  = tid >> 2,          bkq  = tid & 3;

    float acc[2][4][4];
#pragma unroll
    for (int i = 0; i < 2; i++)
#pragma unroll
        for (int j = 0; j < 4; j++)
#pragma unroll
            for (int t = 0; t < 4; t++) acc[i][j][t] = 0.f;

    float4 aR0, aR1, bR;
    // prologue: load stage kbeg
    {
        int k = kbeg + akq0 * 4;
        aR0 = (k < KA0) ? *(const float4*)(A0 + (size_t)am0 * KA0 + k)
                        : *(const float4*)(A1 + (size_t)am0 * KA1 + (k - KA0));
        k = kbeg + akq1 * 4;
        aR1 = (k < KA0) ? *(const float4*)(A0 + (size_t)am1 * KA0 + k)
                        : *(const float4*)(A1 + (size_t)am1 * KA1 + (k - KA0));
        k = kbeg + bkq * 4;
        int gn = n0 + bn;
        bR = (k < KB0) ? *(const float4*)(B0 + (size_t)gn * KB0 + k)
                       : *(const float4*)(B1 + (size_t)gn * KB1 + (k - KB0));
    }

    for (int k0 = kbeg; k0 < kend; k0 += 16) {
        // STS (convert to tf32 bits)
        {
            uint4 w;
            w.x = f2tf32(aR0.x); w.y = f2tf32(aR0.y);
            w.z = f2tf32(aR0.z); w.w = f2tf32(aR0.w);
            *(uint4*)&As[am0 * TP + akq0 * 4] = w;
            w.x = f2tf32(aR1.x); w.y = f2tf32(aR1.y);
            w.z = f2tf32(aR1.z); w.w = f2tf32(aR1.w);
            *(uint4*)&As[am1 * TP + akq1 * 4] = w;
            w.x = f2tf32(bR.x); w.y = f2tf32(bR.y);
            w.z = f2tf32(bR.z); w.w = f2tf32(bR.w);
            *(uint4*)&Bs[bn * TP + bkq * 4] = w;
        }
        __syncthreads();

        // prefetch next stage
        if (k0 + 16 < kend) {
            int k = k0 + 16 + akq0 * 4;
            aR0 = (k < KA0) ? *(const float4*)(A0 + (size_t)am0 * KA0 + k)
                            : *(const float4*)(A1 + (size_t)am0 * KA1 + (k - KA0));
            k = k0 + 16 + akq1 * 4;
            aR1 = (k < KA0) ? *(const float4*)(A0 + (size_t)am1 * KA0 + k)
                            : *(const float4*)(A1 + (size_t)am1 * KA1 + (k - KA0));
            k = k0 + 16 + bkq * 4;
            int gn = n0 + bn;
            bR = (k < KB0) ? *(const float4*)(B0 + (size_t)gn * KB0 + k)
                           : *(const float4*)(B1 + (size_t)gn * KB1 + (k - KB0));
        }

        // compute: 2 k8 sub-steps
#pragma unroll
        for (int ks = 0; ks < 2; ks++) {
            const int kk = ks * 8;
            uint32_t a[2][4];
#pragma unroll
            for (int mi = 0; mi < 2; mi++) {
                int row = wm + mi * 16 + r;
                a[mi][0] = As[row * TP + kk + c];
                a[mi][1] = As[(row + 8) * TP + kk + c];
                a[mi][2] = As[row * TP + kk + c + 4];
                a[mi][3] = As[(row + 8) * TP + kk + c + 4];
            }
            uint32_t b[4][2];
#pragma unroll
            for (int nj = 0; nj < 4; nj++) {
                int rown = wn + nj * 8 + r;
                b[nj][0] = Bs[rown * TP + kk + c];
                b[nj][1] = Bs[rown * TP + kk + c + 4];
            }
#pragma unroll
            for (int mi = 0; mi < 2; mi++)
#pragma unroll
                for (int nj = 0; nj < 4; nj++) {
                    asm volatile(
                        "mma.sync.aligned.m16n8k8.row.col.f32.tf32.tf32.f32 "
                        "{%0,%1,%2,%3}, {%4,%5,%6,%7}, {%8,%9}, {%0,%1,%2,%3};"
                        : "+f"(acc[mi][nj][0]), "+f"(acc[mi][nj][1]),
                          "+f"(acc[mi][nj][2]), "+f"(acc[mi][nj][3])
                        : "r"(a[mi][0]), "r"(a[mi][1]), "r"(a[mi][2]), "r"(a[mi][3]),
                          "r"(b[nj][0]), "r"(b[nj][1]));
                }
        }
        __syncthreads();
    }

    // epilogue: atomic reduce
#pragma unroll
    for (int mi = 0; mi < 2; mi++) {
        int gm = wm + mi * 16 + r;
#pragma unroll
        for (int nj = 0; nj < 4; nj++) {
            int gn = n0 + wn + nj * 8 + c * 2;
            atomicAdd(&C[(size_t)gm * N + gn],           acc[mi][nj][0]);
            atomicAdd(&C[(size_t)gm * N + gn + 1],       acc[mi][nj][1]);
            atomicAdd(&C[(size_t)(gm + 8) * N + gn],     acc[mi][nj][2]);
            atomicAdd(&C[(size_t)(gm + 8) * N + gn + 1], acc[mi][nj][3]);
        }
    }
}

// ---------------------------------------------------------------------------
// Vocab GEMM via bf16 tensor cores, register double-buffered.
// C[128, VV] = A[128,512] * B[VV,512]^T + bias
// ---------------------------------------------------------------------------
#define VPITCH 40   // smem row pitch in bf16 elems (conflict-free LDSM)

__global__ __launch_bounds__(256) void vocab_gemm_mma(
    const __nv_bfloat16* __restrict__ Abf,   // [128][512]
    const float* __restrict__ B,             // [VV][512]
    const float* __restrict__ bias,
    float* __restrict__ C)
{
    __shared__ __nv_bfloat16 As[128 * VPITCH];
    __shared__ __nv_bfloat16 Bs[128 * VPITCH];

    const int tid  = threadIdx.x;
    const int n0   = blockIdx.x * 128;
    const int wid  = tid >> 5;
    const int lane = tid & 31;
    const int warp_m = (wid & 3) * 32;   // 4 warps over m
    const int warp_n = (wid >> 2) * 64;  // 2 warps over n

    const uint32_t as_base = (uint32_t)__cvta_generic_to_shared(As);
    const uint32_t bs_base = (uint32_t)__cvta_generic_to_shared(Bs);

    float acc[2][8][4];
#pragma unroll
    for (int i = 0; i < 2; i++)
#pragma unroll
        for (int j = 0; j < 8; j++)
#pragma unroll
            for (int t = 0; t < 4; t++) acc[i][j][t] = 0.f;

    uint4  aR[2];
    float4 bR[4];

    // prologue: load stage 0
#pragma unroll
    for (int r = 0; r < 2; r++) {
        int slot = tid + r * 256;
        int m = slot >> 2, kq = slot & 3;
        aR[r] = *(const uint4*)(Abf + (size_t)m * 512 + kq * 8);
    }
#pragma unroll
    for (int r = 0; r < 4; r++) {
        int slot = tid + r * 256;
        int n = slot >> 3, c4 = slot & 7;
        int gn = n0 + n;
        bR[r] = make_float4(0.f, 0.f, 0.f, 0.f);
        if (gn < VV) bR[r] = *(const float4*)(B + (size_t)gn * 512 + c4 * 4);
    }

    for (int k0 = 0; k0 < 512; k0 += 32) {
        // STS current stage
#pragma unroll
        for (int r = 0; r < 2; r++) {
            int slot = tid + r * 256;
            int m = slot >> 2, kq = slot & 3;
            *(uint4*)(As + m * VPITCH + kq * 8) = aR[r];
        }
#pragma unroll
        for (int r = 0; r < 4; r++) {
            int slot = tid + r * 256;
            int n = slot >> 3, c4 = slot & 7;
            __nv_bfloat162* dst = (__nv_bfloat162*)(Bs + n * VPITCH + c4 * 4);
            dst[0] = __floats2bfloat162_rn(bR[r].x, bR[r].y);
            dst[1] = __floats2bfloat162_rn(bR[r].z, bR[r].w);
        }
        __syncthreads();

        // prefetch next stage into regs (overlaps with MMA below)
        if (k0 + 32 < 512) {
#pragma unroll
            for (int r = 0; r < 2; r++) {
                int slot = tid + r * 256;
                int m = slot >> 2, kq = slot & 3;
                aR[r] = *(const uint4*)(Abf + (size_t)m * 512 + k0 + 32 + kq * 8);
            }
#pragma unroll
            for (int r = 0; r < 4; r++) {
                int slot = tid + r * 256;
                int n = slot >> 3, c4 = slot & 7;
                int gn = n0 + n;
                bR[r] = make_float4(0.f, 0.f, 0.f, 0.f);
                if (gn < VV)
                    bR[r] = *(const float4*)(B + (size_t)gn * 512 + k0 + 32 + c4 * 4);
            }
        }

#pragma unroll
        for (int kk = 0; kk < 2; kk++) {
            const int kb = kk * 16;
            uint32_t a[2][4];
#pragma unroll
            for (int mi = 0; mi < 2; mi++) {
                int row = warp_m + mi * 16 + (lane & 15);
                int col = kb + (lane >> 4) * 8;
                uint32_t addr = as_base + (row * VPITCH + col) * 2;
                asm volatile(
                    "ldmatrix.sync.aligned.m8n8.x4.shared.b16 {%0,%1,%2,%3}, [%4];"
                    : "=r"(a[mi][0]), "=r"(a[mi][1]), "=r"(a[mi][2]), "=r"(a[mi][3])
                    : "r"(addr));
            }
            uint32_t b[8][2];
#pragma unroll
            for (int nq = 0; nq < 4; nq++) {
                int g = lane >> 3;
                int within = lane & 7;
                int row_n = warp_n + nq * 16 + within + (g >> 1) * 8;
                int colk = kb + (g & 1) * 8;
                uint32_t addr = bs_base + (row_n * VPITCH + colk) * 2;
                uint32_t r0, r1, r2, r3;
                asm volatile(
                    "ldmatrix.sync.aligned.m8n8.x4.shared.b16 {%0,%1,%2,%3}, [%4];"
                    : "=r"(r0), "=r"(r1), "=r"(r2), "=r"(r3)
                    : "r"(addr));
                b[nq * 2 + 0][0] = r0; b[nq * 2 + 0][1] = r1;
                b[nq * 2 + 1][0] = r2; b[nq * 2 + 1][1] = r3;
            }
#pragma unroll
            for (int mi = 0; mi < 2; mi++)
#pragma unroll
                for (int nj = 0; nj < 8; nj++) {
                    asm volatile(
                        "mma.sync.aligned.m16n8k16.row.col.f32.bf16.bf16.f32 "
                        "{%0,%1,%2,%3}, {%4,%5,%6,%7}, {%8,%9}, {%0,%1,%2,%3};"
                        : "+f"(acc[mi][nj][0]), "+f"(acc[mi][nj][1]),
                          "+f"(acc[mi][nj][2]), "+f"(acc[mi][nj][3])
                        : "r"(a[mi][0]), "r"(a[mi][1]), "r"(a[mi][2]), "r"(a[mi][3]),
                          "r"(b[nj][0]), "r"(b[nj][1]));
                }
        }
        __syncthreads();
    }

    // epilogue: bias + store fp32
#pragma unroll
    for (int mi = 0; mi < 2; mi++) {
        int m = warp_m + mi * 16 + (lane >> 2);
#pragma unroll
        for (int nj = 0; nj < 8; nj++) {
            int n = n0 + warp_n + nj * 8 + (lane & 3) * 2;
            if (n < VV)     C[(size_t)m * VV + n]     = acc[mi][nj][0] + bias[n];
            if (n + 1 < VV) C[(size_t)m * VV + n + 1] = acc[mi][nj][1] + bias[n + 1];
            int m2 = m + 8;
            if (n < VV)     C[(size_t)m2 * VV + n]     = acc[mi][nj][2] + bias[n];
            if (n + 1 < VV) C[(size_t)m2 * VV + n + 1] = acc[mi][nj][3] + bias[n + 1];
        }
    }
}

// ---------------------------------------------------------------------------
// LSTM elementwise
// ---------------------------------------------------------------------------
__global__ void lstm_elem(const float* __restrict__ gates,
                          const float* __restrict__ b_hh,
                          const float* __restrict__ c0,
                          float* __restrict__ h1, float* __restrict__ c1,
                          float* __restrict__ out_h1, float* __restrict__ out_c1)
{
    int idx = blockIdx.x * blockDim.x + threadIdx.x;
    if (idx >= BB * HH) return;
    int b = idx / HH, j = idx % HH;
    const float* g = gates + (size_t)b * 4 * HH;
    float iv = sigmoidf_(g[j]          + b_hh[j]);
    float fv = sigmoidf_(g[HH + j]     + b_hh[HH + j]);
    float gv = tanhf(    g[2 * HH + j] + b_hh[2 * HH + j]);
    float ov = sigmoidf_(g[3 * HH + j] + b_hh[3 * HH + j]);
    float c = fv * c0[idx] + iv * gv;
    float h = ov * tanhf(c);
    h1[idx] = h; c1[idx] = c;
    out_h1[idx] = h; out_c1[idx] = c;
}

// ---------------------------------------------------------------------------
// Attention energies (warp per (b,s) row), tanh.approx
// ---------------------------------------------------------------------------
__global__ void attn_e_kernel(const float* __restrict__ sf,
                              const float* __restrict__ dec_fea,
                              const float* __restrict__ cov,
                              const float* __restrict__ mask,
                              const float* __restrict__ v_att,
                              const float* __restrict__ w_c,
                              float* __restrict__ e)
{
    int gwarp = (blockIdx.x * blockDim.x + threadIdx.x) >> 5;
    int lane = threadIdx.x & 31;
    if (gwarp >= BB * SS) return;
    int b = gwarp / SS;
    float cadd = w_c[0] * cov[gwarp];

    const float4* row = (const float4*)(sf + (size_t)gwarp * HH);
    const float4* df  = (const float4*)(dec_fea + (size_t)b * HH);
    const float4* va  = (const float4*)(v_att);

    float acc = 0.f;
#pragma unroll
    for (int i = 0; i < HH / 128; i++) {
        float4 x = row[i * 32 + lane];
        float4 d = df[i * 32 + lane];
        float4 v = va[i * 32 + lane];
        acc += tanh_approx(x.x + d.x + cadd) * v.x;
        acc += tanh_approx(x.y + d.y + cadd) * v.y;
        acc += tanh_approx(x.z + d.z + cadd) * v.z;
        acc += tanh_approx(x.w + d.w + cadd) * v.w;
    }
#pragma unroll
    for (int off = 16; off; off >>= 1) acc += __shfl_xor_sync(0xffffffffu, acc, off);
    if (lane == 0) e[gwarp] = (mask[gwarp] > 0.f) ? acc : -1.0e9f;
}

// ---------------------------------------------------------------------------
// Softmax over S + mask renorm + coverage update
// ---------------------------------------------------------------------------
__global__ void softmax_s_kernel(const float* __restrict__ e,
                                 const float* __restrict__ mask,
                                 const float* __restrict__ cov,
                                 float* __restrict__ attn,
                                 float* __restrict__ out_attn,
                                 float* __restrict__ out_cov)
{
    int b = blockIdx.x;
    int tid = threadIdx.x;           // 512 threads
    __shared__ float sh[SS];
    __shared__ float r1[512];
    __shared__ float r2[512];

    float m = -3.0e38f;
    for (int s = tid; s < SS; s += 512) m = fmaxf(m, e[b * SS + s]);
    r1[tid] = m; __syncthreads();
    for (int off = 256; off; off >>= 1) {
        if (tid < off) r1[tid] = fmaxf(r1[tid], r1[tid + off]);
        __syncthreads();
    }
    m = r1[0];
    __syncthreads();

    float P = 0.f, Q = 0.f;
    for (int s = tid; s < SS; s += 512) {
        float p = __expf(e[b * SS + s] - m);
        sh[s] = p;
        P += p;
        Q += p * mask[b * SS + s];
    }
    r1[tid] = P; r2[tid] = Q; __syncthreads();
    for (int off = 256; off; off >>= 1) {
        if (tid < off) { r1[tid] += r1[tid + off]; r2[tid] += r2[tid + off]; }
        __syncthreads();
    }
    P = r1[0]; Q = r2[0];
    float denom = Q / P + 1e-12f;

    for (int s = tid; s < SS; s += 512) {
        float a = sh[s] * mask[b * SS + s] / P / denom;
        attn[b * SS + s] = a;
        out_attn[b * SS + s] = a;
        out_cov[b * SS + s] = cov[b * SS + s] + a;
    }
}

// ---------------------------------------------------------------------------
// Context: ctx[b,h] = sum_s attn[b,s] * states[b,s,h]
// ---------------------------------------------------------------------------
__global__ void ctx_kernel(const float* __restrict__ attn,
                           const float* __restrict__ states,
                           float* __restrict__ ctx)
{
    int b = blockIdx.x;
    int h = blockIdx.y * 256 + threadIdx.x;
    __shared__ float sa[SS];
    for (int s = threadIdx.x; s < SS; s += 256) sa[s] = attn[b * SS + s];
    __syncthreads();

    const float* st = states + (size_t)b * SS * HH + h;
    float a0 = 0.f, a1 = 0.f, a2 = 0.f, a3 = 0.f;
    for (int s = 0; s < SS; s += 4) {
        a0 += sa[s]     * st[(size_t)(s)     * HH];
        a1 += sa[s + 1] * st[(size_t)(s + 1) * HH];
        a2 += sa[s + 2] * st[(size_t)(s + 2) * HH];
        a3 += sa[s + 3] * st[(size_t)(s + 3) * HH];
    }
    ctx[b * HH + h] = (a0 + a1) + (a2 + a3);
}

// ---------------------------------------------------------------------------
// p_gen = sigmoid(dec_out . W_pg + b_pg); copy dec_out to output; bf16 convert
// ---------------------------------------------------------------------------
__global__ void pgen_kernel(const float* __restrict__ dec_out,
                            const float* __restrict__ W_pg,
                            const float* __restrict__ b_pg,
                            float* __restrict__ pgen,
                            float* __restrict__ out_pgen,
                            float* __restrict__ out_dec,
                            __nv_bfloat16* __restrict__ dec_bf)
{
    int b = blockIdx.x;
    int tid = threadIdx.x;            // 128 threads
    float acc = 0.f;
    for (int j = tid; j < HH; j += 128) {
        float d = dec_out[b * HH + j];
        out_dec[b * HH + j] = d;
        dec_bf[b * HH + j] = __float2bfloat16_rn(d);
        acc += d * W_pg[j];
    }
    __shared__ float red[4];
#pragma unroll
    for (int off = 16; off; off >>= 1) acc += __shfl_xor_sync(0xffffffffu, acc, off);
    if ((tid & 31) == 0) red[tid >> 5] = acc;
    __syncthreads();
    if (tid == 0) {
        float t = red[0] + red[1] + red[2] + red[3];
        float p = sigmoidf_(t + b_pg[0]);
        pgen[b] = p;
        out_pgen[b] = p;
    }
}

// ---------------------------------------------------------------------------
// Row max + sum(exp) over vocab (online), one block per batch row
// ---------------------------------------------------------------------------
__global__ void vocab_stats_kernel(const float* __restrict__ logits,
                                   float* __restrict__ rowm,
                                   float* __restrict__ rows)
{
    int b = blockIdx.x;
    int tid = threadIdx.x;    // 512
    float m = -3.0e38f, s = 0.f;
    for (int v = tid; v < VV; v += 512) {
        float x = logits[(size_t)b * VV + v];
        if (x > m) {
            s = s * __expf(m - x) + 1.f;
            m = x;
        } else {
            s += __expf(x - m);
        }
    }
    __shared__ float sm[512], ssum[512];
    sm[tid] = m; ssum[tid] = s; __syncthreads();
    for (int off = 256; off; off >>= 1) {
        if (tid < off) {
            float m2 = sm[tid + off], s2 = ssum[tid + off];
            float M = fmaxf(sm[tid], m2);
            ssum[tid] = ssum[tid] * __expf(sm[tid] - M) + s2 * __expf(m2 - M);
            sm[tid] = M;
        }
        __syncthreads();
    }
    if (tid == 0) { rowm[b] = sm[0]; rows[b] = ssum[0]; }
}

// ---------------------------------------------------------------------------
// Final vocab distribution (p_gen * softmax, OOV zeros)
// ---------------------------------------------------------------------------
__global__ void final_vocab_kernel(const float* __restrict__ logits,
                                   const float* __restrict__ rowm,
                                   const float* __restrict__ rows,
                                   const float* __restrict__ pgen,
                                   float* __restrict__ outf)
{
    long idx = (long)blockIdx.x * blockDim.x + threadIdx.x;
    if (idx >= (long)BB * VEXTN) return;
    int b = (int)(idx / VEXTN);
    int n = (int)(idx % VEXTN);
    float val = 0.f;
    if (n < VV) {
        float scale = pgen[b] / rows[b];
        val = scale * __expf(logits[(size_t)b * VV + n] - rowm[b]);
    }
    outf[idx] = val;
}

// ---------------------------------------------------------------------------
// Copy-mechanism scatter
// ---------------------------------------------------------------------------
__global__ void scatter_kernel(const int* __restrict__ ids,
                               const float* __restrict__ attn,
                               const float* __restrict__ pgen,
                               float* __restrict__ outf)
{
    int idx = blockIdx.x * blockDim.x + threadIdx.x;
    if (idx >= BB * SS) return;
    int b = idx / SS;
    float v = (1.f - pgen[b]) * attn[idx];
    atomicAdd(&outf[(size_t)b * VEXTN + ids[idx]], v);
}

// ---------------------------------------------------------------------------
// Launcher
// ---------------------------------------------------------------------------
extern "C" void kernel_launch(void* const* d_in, const int* in_sizes, int n_in,
                              void* d_out, int out_size)
{
    const float* emb    = (const float*)d_in[0];
    const float* feed   = (const float*)d_in[1];
    const float* hidden = (const float*)d_in[2];
    const float* ctx0   = (const float*)d_in[3];
    const float* states = (const float*)d_in[4];
    const float* sfeat  = (const float*)d_in[5];
    const float* mask   = (const float*)d_in[6];
    const float* cov    = (const float*)d_in[7];
    const int*   srcids = (const int*)d_in[8];
    const float* W_ic   = (const float*)d_in[9];
    const float* b_ic   = (const float*)d_in[10];
    const float* W_ih   = (const float*)d_in[11];
    const float* W_hh   = (const float*)d_in[12];
    const float* b_ih   = (const float*)d_in[13];
    const float* b_hh   = (const float*)d_in[14];
    const float* W_dec  = (const float*)d_in[15];
    const float* b_att  = (const float*)d_in[16];
    const float* v_att  = (const float*)d_in[17];
    const float* w_c    = (const float*)d_in[18];
    const float* W_out  = (const float*)d_in[19];
    const float* b_out  = (const float*)d_in[20];
    const float* W_pg   = (const float*)d_in[21];
    const float* b_pg   = (const float*)d_in[22];
    const float* W_v    = (const float*)d_in[23];
    const float* b_v    = (const float*)d_in[24];

    float* out = (float*)d_out;
    float* out_final = out;
    float* out_pgen  = out_final + (size_t)BB * VEXTN;
    float* out_attn  = out_pgen + BB;
    float* out_cov   = out_attn + (size_t)BB * SS;
    float* out_h1    = out_cov + (size_t)BB * SS;
    float* out_c1    = out_h1 + (size_t)BB * HH;
    float* out_dec   = out_c1 + (size_t)BB * HH;

    float *px, *pgates, *ph1, *pc1, *pdecfea, *pctx, *pdecout;
    float *pe, *pattn, *ppgen, *prowm, *prows, *plogits;
    __nv_bfloat16* pdecbf;
    cudaGetSymbolAddress((void**)&px,      g_x);
    cudaGetSymbolAddress((void**)&pgates,  g_gates);
    cudaGetSymbolAddress((void**)&ph1,     g_h1);
    cudaGetSymbolAddress((void**)&pc1,     g_c1);
    cudaGetSymbolAddress((void**)&pdecfea, g_decfea);
    cudaGetSymbolAddress((void**)&pctx,    g_ctx);
    cudaGetSymbolAddress((void**)&pdecout, g_decout);
    cudaGetSymbolAddress((void**)&pdecbf,  g_dec_bf);
    cudaGetSymbolAddress((void**)&pe,      g_e);
    cudaGetSymbolAddress((void**)&pattn,   g_attn);
    cudaGetSymbolAddress((void**)&ppgen,   g_pgen);
    cudaGetSymbolAddress((void**)&prowm,   g_rowm);
    cudaGetSymbolAddress((void**)&prows,   g_rows);
    cudaGetSymbolAddress((void**)&plogits, g_logits);

    // 0) all bias fills fused (458752 elements)
    fill_bias_all<<<(458752 + 255) / 256, 256>>>(px, b_ic, pgates, b_ih,
                                                 pdecfea, b_att, pdecout, b_out);

    // 1) x = [emb|feed] @ W_ic^T   (128 x 512, K=1024), tf32, split 8
    gemm_tf32_splitk<<<dim3(EE / 64, 1, 8), 256>>>(
        EE, 1024, 128, emb, EE, feed, W_ic, 1024, nullptr, px);

    // 2) gates = [x|h0] @ [W_ih|W_hh]^T   (128 x 2048, K=1024), tf32, split 8
    gemm_tf32_splitk<<<dim3(4 * HH / 64, 1, 8), 256>>>(
        4 * HH, 1024, 128, px, EE, hidden, W_ih, EE, W_hh, pgates);

    // 3) LSTM elementwise
    lstm_elem<<<(BB * HH + 255) / 256, 256>>>(pgates, b_hh, ctx0, ph1, pc1,
                                              out_h1, out_c1);

    // 4) dec_fea = h1 @ W_dec^T   (128 x 512, K=512), tf32, split 8
    gemm_tf32_splitk<<<dim3(HH / 64, 1, 8), 256>>>(
        HH, 512, 64, ph1, 512, nullptr, W_dec, 512, nullptr, pdecfea);

    // 5) attention energies
    attn_e_kernel<<<(BB * SS) / 8, 256>>>(sfeat, pdecfea, cov, mask, v_att, w_c, pe);

    // 6) softmax over S + coverage update
    softmax_s_kernel<<<BB, 512>>>(pe, mask, cov, pattn, out_attn, out_cov);

    // 7) context vector
    ctx_kernel<<<dim3(BB, 2), 256>>>(pattn, states, pctx);

    // 8) dec_out = [h1|ctx] @ W_out^T   (128 x 512, K=1024), tf32, split 8
    gemm_tf32_splitk<<<dim3(HH / 64, 1, 8), 256>>>(
        HH, 1024, 128, ph1, HH, pctx, W_out, 1024, nullptr, pdecout);

    // 9) p_gen + dec_out output copy + bf16 convert
    pgen_kernel<<<BB, 128>>>(pdecout, W_pg, b_pg, ppgen, out_pgen, out_dec, pdecbf);

    // 10) vocab logits = dec_out @ W_v^T + b_v   (bf16 tensor cores)
    vocab_gemm_mma<<<(VV + 127) / 128, 256>>>(pdecbf, W_v, b_v, plogits);

    // 11) vocab softmax stats
    vocab_stats_kernel<<<BB, 512>>>(plogits, prowm, prows);

    // 12) final vocab distribution (incl. zero OOV tail)
    {
        long total = (long)BB * VEXTN;
        final_vocab_kernel<<<(int)((total + 255) / 256), 256>>>(
            plogits, prowm, prows, ppgen, out_final);
    }

    // 13) copy scatter
    scatter_kernel<<<(BB * SS + 255) / 256, 256>>>(srcids, pattn, ppgen, out_final);
}

// round 5
// speedup vs baseline: 7.6977x; 1.0342x over previous
#include <cuda_runtime.h>
#include <cuda_bf16.h>
#include <math.h>
#include <stdint.h>

// Problem constants
#define BB   128
#define SS   400
#define EE   512
#define HH   512
#define VV   50257
#define NOOV 50
#define VEXTN (VV + NOOV)   // 50307
#define NPB  ((VV + 127) / 128)   // 393 vocab-gemm blocks
#define NPART (NPB * 2)           // 786 partials per row (2 n-warps per block)

// ---------------------------------------------------------------------------
// Scratch (device globals: allocation-free per harness rules)
// ---------------------------------------------------------------------------
__device__ float g_x[BB * EE];
__device__ float g_gates[BB * 4 * HH];
__device__ float g_h1[BB * HH];
__device__ float g_c1[BB * HH];
__device__ float g_decfea[BB * HH];
__device__ float g_ctx[BB * HH];
__device__ float g_decout[BB * HH];
__device__ __nv_bfloat16 g_dec_bf[BB * HH];
__device__ float g_e[BB * SS];
__device__ float g_attn[BB * SS];
__device__ float g_pgen[BB];
__device__ float g_rowm[BB];
__device__ float g_rows[BB];
__device__ float g_pmax[NPART * BB];
__device__ float g_psum[NPART * BB];
__device__ float g_logits[(size_t)BB * VV];   // 25.7 MB

__device__ __forceinline__ float sigmoidf_(float x) {
    return 1.f / (1.f + expf(-x));
}
__device__ __forceinline__ float tanh_approx(float x) {
    float y;
    asm("tanh.approx.f32 %0, %1;" : "=f"(y) : "f"(x));
    return y;
}
__device__ __forceinline__ uint32_t f2tf32(float x) {
    uint32_t o;
    asm("cvt.rna.tf32.f32 %0, %1;" : "=r"(o) : "f"(x));
    return o;
}

// ---------------------------------------------------------------------------
// Fused init: bias broadcasts for 4 GEMM outputs + zero ctx accumulator.
// ---------------------------------------------------------------------------
__global__ void fill_bias_all(float* __restrict__ px, const float* __restrict__ b_ic,
                              float* __restrict__ pgates, const float* __restrict__ b_ih,
                              float* __restrict__ pdecfea, const float* __restrict__ b_att,
                              float* __restrict__ pdecout, const float* __restrict__ b_out,
                              float* __restrict__ pctx)
{
    int i = blockIdx.x * blockDim.x + threadIdx.x;   // < 524288
    if (i < 65536) {
        px[i] = b_ic[i & 511];
    } else if (i < 327680) {
        int j = i - 65536;
        pgates[j] = b_ih[j & 2047];
    } else if (i < 393216) {
        int j = i - 327680;
        pdecfea[j] = b_att[j & 511];
    } else if (i < 458752) {
        int j = i - 393216;
        pdecout[j] = b_out[j & 511];
    } else if (i < 524288) {
        pctx[i - 458752] = 0.f;
    }
}

// ---------------------------------------------------------------------------
// Small GEMM via tf32 tensor cores, split-K with fp32 atomic reduce.
// C[128, N] += Acat[128,K] * Bcat[N,K]^T
// ---------------------------------------------------------------------------
#define TP 20   // smem pitch in words

__global__ __launch_bounds__(256) void gemm_tf32_splitk(
    int N, int K, int kchunk,
    const float* __restrict__ A0, int KA0, const float* __restrict__ A1,
    const float* __restrict__ B0, int KB0, const float* __restrict__ B1,
    float* __restrict__ C)
{
    __shared__ uint32_t As[128 * TP];
    __shared__ uint32_t Bs[64 * TP];

    const int tid  = threadIdx.x;
    const int n0   = blockIdx.x * 64;
    const int kbeg = blockIdx.z * kchunk;
    const int kend = kbeg + kchunk;
    const int wid  = tid >> 5;
    const int lane = tid & 31;
    const int wm   = (wid & 3) * 32;
    const int wn   = (wid >> 2) * 32;
    const int r    = lane >> 2;
    const int c    = lane & 3;
    const int KA1  = K - KA0;
    const int KB1  = K - KB0;

    const int am0 = (tid) >> 2,        akq0 = (tid) & 3;
    const int am1 = (tid + 256) >> 2,  akq1 = (tid + 256) & 3;
    const int bn  = tid >> 2,          bkq  = tid & 3;

    float acc[2][4][4];
#pragma unroll
    for (int i = 0; i < 2; i++)
#pragma unroll
        for (int j = 0; j < 4; j++)
#pragma unroll
            for (int t = 0; t < 4; t++) acc[i][j][t] = 0.f;

    float4 aR0, aR1, bR;
    {
        int k = kbeg + akq0 * 4;
        aR0 = (k < KA0) ? *(const float4*)(A0 + (size_t)am0 * KA0 + k)
                        : *(const float4*)(A1 + (size_t)am0 * KA1 + (k - KA0));
        k = kbeg + akq1 * 4;
        aR1 = (k < KA0) ? *(const float4*)(A0 + (size_t)am1 * KA0 + k)
                        : *(const float4*)(A1 + (size_t)am1 * KA1 + (k - KA0));
        k = kbeg + bkq * 4;
        int gn = n0 + bn;
        bR = (k < KB0) ? *(const float4*)(B0 + (size_t)gn * KB0 + k)
                       : *(const float4*)(B1 + (size_t)gn * KB1 + (k - KB0));
    }

    for (int k0 = kbeg; k0 < kend; k0 += 16) {
        {
            uint4 w;
            w.x = f2tf32(aR0.x); w.y = f2tf32(aR0.y);
            w.z = f2tf32(aR0.z); w.w = f2tf32(aR0.w);
            *(uint4*)&As[am0 * TP + akq0 * 4] = w;
            w.x = f2tf32(aR1.x); w.y = f2tf32(aR1.y);
            w.z = f2tf32(aR1.z); w.w = f2tf32(aR1.w);
            *(uint4*)&As[am1 * TP + akq1 * 4] = w;
            w.x = f2tf32(bR.x); w.y = f2tf32(bR.y);
            w.z = f2tf32(bR.z); w.w = f2tf32(bR.w);
            *(uint4*)&Bs[bn * TP + bkq * 4] = w;
        }
        __syncthreads();

        if (k0 + 16 < kend) {
            int k = k0 + 16 + akq0 * 4;
            aR0 = (k < KA0) ? *(const float4*)(A0 + (size_t)am0 * KA0 + k)
                            : *(const float4*)(A1 + (size_t)am0 * KA1 + (k - KA0));
            k = k0 + 16 + akq1 * 4;
            aR1 = (k < KA0) ? *(const float4*)(A0 + (size_t)am1 * KA0 + k)
                            : *(const float4*)(A1 + (size_t)am1 * KA1 + (k - KA0));
            k = k0 + 16 + bkq * 4;
            int gn = n0 + bn;
            bR = (k < KB0) ? *(const float4*)(B0 + (size_t)gn * KB0 + k)
                           : *(const float4*)(B1 + (size_t)gn * KB1 + (k - KB0));
        }

#pragma unroll
        for (int ks = 0; ks < 2; ks++) {
            const int kk = ks * 8;
            uint32_t a[2][4];
#pragma unroll
            for (int mi = 0; mi < 2; mi++) {
                int row = wm + mi * 16 + r;
                a[mi][0] = As[row * TP + kk + c];
                a[mi][1] = As[(row + 8) * TP + kk + c];
                a[mi][2] = As[row * TP + kk + c + 4];
                a[mi][3] = As[(row + 8) * TP + kk + c + 4];
            }
            uint32_t b[4][2];
#pragma unroll
            for (int nj = 0; nj < 4; nj++) {
                int rown = wn + nj * 8 + r;
                b[nj][0] = Bs[rown * TP + kk + c];
                b[nj][1] = Bs[rown * TP + kk + c + 4];
            }
#pragma unroll
            for (int mi = 0; mi < 2; mi++)
#pragma unroll
                for (int nj = 0; nj < 4; nj++) {
                    asm volatile(
                        "mma.sync.aligned.m16n8k8.row.col.f32.tf32.tf32.f32 "
                        "{%0,%1,%2,%3}, {%4,%5,%6,%7}, {%8,%9}, {%0,%1,%2,%3};"
                        : "+f"(acc[mi][nj][0]), "+f"(acc[mi][nj][1]),
                          "+f"(acc[mi][nj][2]), "+f"(acc[mi][nj][3])
                        : "r"(a[mi][0]), "r"(a[mi][1]), "r"(a[mi][2]), "r"(a[mi][3]),
                          "r"(b[nj][0]), "r"(b[nj][1]));
                }
        }
        __syncthreads();
    }

#pragma unroll
    for (int mi = 0; mi < 2; mi++) {
        int gm = wm + mi * 16 + r;
#pragma unroll
        for (int nj = 0; nj < 4; nj++) {
            int gn = n0 + wn + nj * 8 + c * 2;
            atomicAdd(&C[(size_t)gm * N + gn],           acc[mi][nj][0]);
            atomicAdd(&C[(size_t)gm * N + gn + 1],       acc[mi][nj][1]);
            atomicAdd(&C[(size_t)(gm + 8) * N + gn],     acc[mi][nj][2]);
            atomicAdd(&C[(size_t)(gm + 8) * N + gn + 1], acc[mi][nj][3]);
        }
    }
}

// ---------------------------------------------------------------------------
// online softmax helpers
// ---------------------------------------------------------------------------
__device__ __forceinline__ void online_upd(float& m, float& s, float v) {
    if (v > m) { s = s * __expf(m - v) + 1.f; m = v; }
    else       { s += __expf(v - m); }
}
__device__ __forceinline__ void online_merge(float& m, float& s, float m2, float s2) {
    float M = fmaxf(m, m2);
    s = s * __expf(m - M) + s2 * __expf(m2 - M);
    m = M;
}

// ---------------------------------------------------------------------------
// Vocab GEMM (bf16 MMA, register double-buffered) with fused softmax partials.
// Writes logits and per-(row, n-warp) online (max, sumexp) partials.
// ---------------------------------------------------------------------------
#define VPITCH 40

__global__ __launch_bounds__(256) void vocab_gemm_mma(
    const __nv_bfloat16* __restrict__ Abf,   // [128][512]
    const float* __restrict__ B,             // [VV][512]
    const float* __restrict__ bias,
    float* __restrict__ C,
    float* __restrict__ pmax,
    float* __restrict__ psum)
{
    __shared__ __nv_bfloat16 As[128 * VPITCH];
    __shared__ __nv_bfloat16 Bs[128 * VPITCH];

    const int tid  = threadIdx.x;
    const int n0   = blockIdx.x * 128;
    const int wid  = tid >> 5;
    const int lane = tid & 31;
    const int warp_m = (wid & 3) * 32;
    const int warp_n = (wid >> 2) * 64;

    const uint32_t as_base = (uint32_t)__cvta_generic_to_shared(As);
    const uint32_t bs_base = (uint32_t)__cvta_generic_to_shared(Bs);

    float acc[2][8][4];
#pragma unroll
    for (int i = 0; i < 2; i++)
#pragma unroll
        for (int j = 0; j < 8; j++)
#pragma unroll
            for (int t = 0; t < 4; t++) acc[i][j][t] = 0.f;

    uint4  aR[2];
    float4 bR[4];

#pragma unroll
    for (int r = 0; r < 2; r++) {
        int slot = tid + r * 256;
        int m = slot >> 2, kq = slot & 3;
        aR[r] = *(const uint4*)(Abf + (size_t)m * 512 + kq * 8);
    }
#pragma unroll
    for (int r = 0; r < 4; r++) {
        int slot = tid + r * 256;
        int n = slot >> 3, c4 = slot & 7;
        int gn = n0 + n;
        bR[r] = make_float4(0.f, 0.f, 0.f, 0.f);
        if (gn < VV) bR[r] = *(const float4*)(B + (size_t)gn * 512 + c4 * 4);
    }

    for (int k0 = 0; k0 < 512; k0 += 32) {
#pragma unroll
        for (int r = 0; r < 2; r++) {
            int slot = tid + r * 256;
            int m = slot >> 2, kq = slot & 3;
            *(uint4*)(As + m * VPITCH + kq * 8) = aR[r];
        }
#pragma unroll
        for (int r = 0; r < 4; r++) {
            int slot = tid + r * 256;
            int n = slot >> 3, c4 = slot & 7;
            __nv_bfloat162* dst = (__nv_bfloat162*)(Bs + n * VPITCH + c4 * 4);
            dst[0] = __floats2bfloat162_rn(bR[r].x, bR[r].y);
            dst[1] = __floats2bfloat162_rn(bR[r].z, bR[r].w);
        }
        __syncthreads();

        if (k0 + 32 < 512) {
#pragma unroll
            for (int r = 0; r < 2; r++) {
                int slot = tid + r * 256;
                int m = slot >> 2, kq = slot & 3;
                aR[r] = *(const uint4*)(Abf + (size_t)m * 512 + k0 + 32 + kq * 8);
            }
#pragma unroll
            for (int r = 0; r < 4; r++) {
                int slot = tid + r * 256;
                int n = slot >> 3, c4 = slot & 7;
                int gn = n0 + n;
                bR[r] = make_float4(0.f, 0.f, 0.f, 0.f);
                if (gn < VV)
                    bR[r] = *(const float4*)(B + (size_t)gn * 512 + k0 + 32 + c4 * 4);
            }
        }

#pragma unroll
        for (int kk = 0; kk < 2; kk++) {
            const int kb = kk * 16;
            uint32_t a[2][4];
#pragma unroll
            for (int mi = 0; mi < 2; mi++) {
                int row = warp_m + mi * 16 + (lane & 15);
                int col = kb + (lane >> 4) * 8;
                uint32_t addr = as_base + (row * VPITCH + col) * 2;
                asm volatile(
                    "ldmatrix.sync.aligned.m8n8.x4.shared.b16 {%0,%1,%2,%3}, [%4];"
                    : "=r"(a[mi][0]), "=r"(a[mi][1]), "=r"(a[mi][2]), "=r"(a[mi][3])
                    : "r"(addr));
            }
            uint32_t b[8][2];
#pragma unroll
            for (int nq = 0; nq < 4; nq++) {
                int g = lane >> 3;
                int within = lane & 7;
                int row_n = warp_n + nq * 16 + within + (g >> 1) * 8;
                int colk = kb + (g & 1) * 8;
                uint32_t addr = bs_base + (row_n * VPITCH + colk) * 2;
                uint32_t r0, r1, r2, r3;
                asm volatile(
                    "ldmatrix.sync.aligned.m8n8.x4.shared.b16 {%0,%1,%2,%3}, [%4];"
                    : "=r"(r0), "=r"(r1), "=r"(r2), "=r"(r3)
                    : "r"(addr));
                b[nq * 2 + 0][0] = r0; b[nq * 2 + 0][1] = r1;
                b[nq * 2 + 1][0] = r2; b[nq * 2 + 1][1] = r3;
            }
#pragma unroll
            for (int mi = 0; mi < 2; mi++)
#pragma unroll
                for (int nj = 0; nj < 8; nj++) {
                    asm volatile(
                        "mma.sync.aligned.m16n8k16.row.col.f32.bf16.bf16.f32 "
                        "{%0,%1,%2,%3}, {%4,%5,%6,%7}, {%8,%9}, {%0,%1,%2,%3};"
                        : "+f"(acc[mi][nj][0]), "+f"(acc[mi][nj][1]),
                          "+f"(acc[mi][nj][2]), "+f"(acc[mi][nj][3])
                        : "r"(a[mi][0]), "r"(a[mi][1]), "r"(a[mi][2]), "r"(a[mi][3]),
                          "r"(b[nj][0]), "r"(b[nj][1]));
                }
        }
        __syncthreads();
    }

    // epilogue: bias + store + per-row online stats
    const int pblock = blockIdx.x * 2 + (warp_n ? 1 : 0);
#pragma unroll
    for (int mi = 0; mi < 2; mi++) {
        int m = warp_m + mi * 16 + (lane >> 2);
        float m0v = -3.0e38f, s0 = 0.f;   // row m
        float m1v = -3.0e38f, s1 = 0.f;   // row m+8
#pragma unroll
        for (int nj = 0; nj < 8; nj++) {
            int n = n0 + warp_n + nj * 8 + (lane & 3) * 2;
            if (n < VV) {
                float v = acc[mi][nj][0] + bias[n];
                C[(size_t)m * VV + n] = v;
                online_upd(m0v, s0, v);
                float w = acc[mi][nj][2] + bias[n];
                C[(size_t)(m + 8) * VV + n] = w;
                online_upd(m1v, s1, w);
            }
            if (n + 1 < VV) {
                float v = acc[mi][nj][1] + bias[n + 1];
                C[(size_t)m * VV + n + 1] = v;
                online_upd(m0v, s0, v);
                float w = acc[mi][nj][3] + bias[n + 1];
                C[(size_t)(m + 8) * VV + n + 1] = w;
                online_upd(m1v, s1, w);
            }
        }
        // merge across the 4 lanes (c = lane&3) that share each row
#pragma unroll
        for (int off = 1; off <= 2; off <<= 1) {
            float om = __shfl_xor_sync(0xffffffffu, m0v, off);
            float os = __shfl_xor_sync(0xffffffffu, s0, off);
            online_merge(m0v, s0, om, os);
            om = __shfl_xor_sync(0xffffffffu, m1v, off);
            os = __shfl_xor_sync(0xffffffffu, s1, off);
            online_merge(m1v, s1, om, os);
        }
        if ((lane & 3) == 0) {
            pmax[(size_t)pblock * BB + m]     = m0v;
            psum[(size_t)pblock * BB + m]     = s0;
            pmax[(size_t)pblock * BB + m + 8] = m1v;
            psum[(size_t)pblock * BB + m + 8] = s1;
        }
    }
}

// ---------------------------------------------------------------------------
// Reduce softmax partials: one block per batch row.
// ---------------------------------------------------------------------------
__global__ void reduce_stats_kernel(const float* __restrict__ pmax,
                                    const float* __restrict__ psum,
                                    float* __restrict__ rowm,
                                    float* __restrict__ rows)
{
    int b = blockIdx.x;
    int tid = threadIdx.x;   // 256
    float m = -3.0e38f, s = 0.f;
    for (int i = tid; i < NPART; i += 256)
        online_merge(m, s, pmax[(size_t)i * BB + b], psum[(size_t)i * BB + b]);
    __shared__ float sm[256], ss[256];
    sm[tid] = m; ss[tid] = s; __syncthreads();
    for (int off = 128; off; off >>= 1) {
        if (tid < off) {
            float M = fmaxf(sm[tid], sm[tid + off]);
            ss[tid] = ss[tid] * __expf(sm[tid] - M) + ss[tid + off] * __expf(sm[tid + off] - M);
            sm[tid] = M;
        }
        __syncthreads();
    }
    if (tid == 0) { rowm[b] = sm[0]; rows[b] = ss[0]; }
}

// ---------------------------------------------------------------------------
// LSTM elementwise (float4 vectorized)
// ---------------------------------------------------------------------------
__global__ void lstm_elem(const float* __restrict__ gates,
                          const float* __restrict__ b_hh,
                          const float* __restrict__ c0,
                          float* __restrict__ h1, float* __restrict__ c1,
                          float* __restrict__ out_h1, float* __restrict__ out_c1)
{
    int idx = blockIdx.x * blockDim.x + threadIdx.x;   // < BB*HH/4
    if (idx >= BB * HH / 4) return;
    int b  = idx / (HH / 4);
    int j  = (idx % (HH / 4)) * 4;
    const float* g = gates + (size_t)b * 4 * HH;
    float4 gi = *(const float4*)(g + j);
    float4 gf = *(const float4*)(g + HH + j);
    float4 gg = *(const float4*)(g + 2 * HH + j);
    float4 go = *(const float4*)(g + 3 * HH + j);
    float4 bi = *(const float4*)(b_hh + j);
    float4 bf = *(const float4*)(b_hh + HH + j);
    float4 bg = *(const float4*)(b_hh + 2 * HH + j);
    float4 bo = *(const float4*)(b_hh + 3 * HH + j);
    float4 cprev = *(const float4*)(c0 + b * HH + j);

    float4 cc, hh;
    {
        float iv = sigmoidf_(gi.x + bi.x), fv = sigmoidf_(gf.x + bf.x);
        float gv = tanhf(gg.x + bg.x),     ov = sigmoidf_(go.x + bo.x);
        cc.x = fv * cprev.x + iv * gv; hh.x = ov * tanhf(cc.x);
        iv = sigmoidf_(gi.y + bi.y); fv = sigmoidf_(gf.y + bf.y);
        gv = tanhf(gg.y + bg.y);     ov = sigmoidf_(go.y + bo.y);
        cc.y = fv * cprev.y + iv * gv; hh.y = ov * tanhf(cc.y);
        iv = sigmoidf_(gi.z + bi.z); fv = sigmoidf_(gf.z + bf.z);
        gv = tanhf(gg.z + bg.z);     ov = sigmoidf_(go.z + bo.z);
        cc.z = fv * cprev.z + iv * gv; hh.z = ov * tanhf(cc.z);
        iv = sigmoidf_(gi.w + bi.w); fv = sigmoidf_(gf.w + bf.w);
        gv = tanhf(gg.w + bg.w);     ov = sigmoidf_(go.w + bo.w);
        cc.w = fv * cprev.w + iv * gv; hh.w = ov * tanhf(cc.w);
    }
    *(float4*)(h1 + b * HH + j) = hh;
    *(float4*)(c1 + b * HH + j) = cc;
    *(float4*)(out_h1 + b * HH + j) = hh;
    *(float4*)(out_c1 + b * HH + j) = cc;
}

// ---------------------------------------------------------------------------
// Attention energies (warp per (b,s) row), tanh.approx
// ---------------------------------------------------------------------------
__global__ void attn_e_kernel(const float* __restrict__ sf,
                              const float* __restrict__ dec_fea,
                              const float* __restrict__ cov,
                              const float* __restrict__ mask,
                              const float* __restrict__ v_att,
                              const float* __restrict__ w_c,
                              float* __restrict__ e)
{
    int gwarp = (blockIdx.x * blockDim.x + threadIdx.x) >> 5;
    int lane = threadIdx.x & 31;
    if (gwarp >= BB * SS) return;
    int b = gwarp / SS;
    float cadd = w_c[0] * cov[gwarp];

    const float4* row = (const float4*)(sf + (size_t)gwarp * HH);
    const float4* df  = (const float4*)(dec_fea + (size_t)b * HH);
    const float4* va  = (const float4*)(v_att);

    float acc = 0.f;
#pragma unroll
    for (int i = 0; i < HH / 128; i++) {
        float4 x = row[i * 32 + lane];
        float4 d = df[i * 32 + lane];
        float4 v = va[i * 32 + lane];
        acc += tanh_approx(x.x + d.x + cadd) * v.x;
        acc += tanh_approx(x.y + d.y + cadd) * v.y;
        acc += tanh_approx(x.z + d.z + cadd) * v.z;
        acc += tanh_approx(x.w + d.w + cadd) * v.w;
    }
#pragma unroll
    for (int off = 16; off; off >>= 1) acc += __shfl_xor_sync(0xffffffffu, acc, off);
    if (lane == 0) e[gwarp] = (mask[gwarp] > 0.f) ? acc : -1.0e9f;
}

// ---------------------------------------------------------------------------
// Softmax over S + mask renorm + coverage update
// ---------------------------------------------------------------------------
__global__ void softmax_s_kernel(const float* __restrict__ e,
                                 const float* __restrict__ mask,
                                 const float* __restrict__ cov,
                                 float* __restrict__ attn,
                                 float* __restrict__ out_attn,
                                 float* __restrict__ out_cov)
{
    int b = blockIdx.x;
    int tid = threadIdx.x;           // 512 threads
    __shared__ float sh[SS];
    __shared__ float r1[512];
    __shared__ float r2[512];

    float m = -3.0e38f;
    for (int s = tid; s < SS; s += 512) m = fmaxf(m, e[b * SS + s]);
    r1[tid] = m; __syncthreads();
    for (int off = 256; off; off >>= 1) {
        if (tid < off) r1[tid] = fmaxf(r1[tid], r1[tid + off]);
        __syncthreads();
    }
    m = r1[0];
    __syncthreads();

    float P = 0.f, Q = 0.f;
    for (int s = tid; s < SS; s += 512) {
        float p = __expf(e[b * SS + s] - m);
        sh[s] = p;
        P += p;
        Q += p * mask[b * SS + s];
    }
    r1[tid] = P; r2[tid] = Q; __syncthreads();
    for (int off = 256; off; off >>= 1) {
        if (tid < off) { r1[tid] += r1[tid + off]; r2[tid] += r2[tid + off]; }
        __syncthreads();
    }
    P = r1[0]; Q = r2[0];
    float denom = Q / P + 1e-12f;

    for (int s = tid; s < SS; s += 512) {
        float a = sh[s] * mask[b * SS + s] / P / denom;
        attn[b * SS + s] = a;
        out_attn[b * SS + s] = a;
        out_cov[b * SS + s] = cov[b * SS + s] + a;
    }
}

// ---------------------------------------------------------------------------
// Context: ctx[b,h] += sum_{s in chunk} attn[b,s]*states[b,s,h]; grid (B,2,4)
// ---------------------------------------------------------------------------
#define CSPLIT 4
#define CCHUNK (SS / CSPLIT)   // 100

__global__ void ctx_kernel(const float* __restrict__ attn,
                           const float* __restrict__ states,
                           float* __restrict__ ctx)
{
    int b = blockIdx.x;
    int h = blockIdx.y * 256 + threadIdx.x;
    int s0 = blockIdx.z * CCHUNK;
    __shared__ float sa[CCHUNK];
    for (int s = threadIdx.x; s < CCHUNK; s += 256) sa[s] = attn[b * SS + s0 + s];
    __syncthreads();

    const float* st = states + (size_t)b * SS * HH + (size_t)s0 * HH + h;
    float a0 = 0.f, a1 = 0.f, a2 = 0.f, a3 = 0.f;
    for (int s = 0; s < CCHUNK; s += 4) {
        a0 += sa[s]     * st[(size_t)(s)     * HH];
        a1 += sa[s + 1] * st[(size_t)(s + 1) * HH];
        a2 += sa[s + 2] * st[(size_t)(s + 2) * HH];
        a3 += sa[s + 3] * st[(size_t)(s + 3) * HH];
    }
    atomicAdd(&ctx[b * HH + h], (a0 + a1) + (a2 + a3));
}

// ---------------------------------------------------------------------------
// p_gen = sigmoid(dec_out . W_pg + b_pg); copy dec_out to output; bf16 convert
// ---------------------------------------------------------------------------
__global__ void pgen_kernel(const float* __restrict__ dec_out,
                            const float* __restrict__ W_pg,
                            const float* __restrict__ b_pg,
                            float* __restrict__ pgen,
                            float* __restrict__ out_pgen,
                            float* __restrict__ out_dec,
                            __nv_bfloat16* __restrict__ dec_bf)
{
    int b = blockIdx.x;
    int tid = threadIdx.x;            // 128 threads
    float acc = 0.f;
    for (int j = tid; j < HH; j += 128) {
        float d = dec_out[b * HH + j];
        out_dec[b * HH + j] = d;
        dec_bf[b * HH + j] = __float2bfloat16_rn(d);
        acc += d * W_pg[j];
    }
    __shared__ float red[4];
#pragma unroll
    for (int off = 16; off; off >>= 1) acc += __shfl_xor_sync(0xffffffffu, acc, off);
    if ((tid & 31) == 0) red[tid >> 5] = acc;
    __syncthreads();
    if (tid == 0) {
        float t = red[0] + red[1] + red[2] + red[3];
        float p = sigmoidf_(t + b_pg[0]);
        pgen[b] = p;
        out_pgen[b] = p;
    }
}

// ---------------------------------------------------------------------------
// Final vocab distribution (p_gen * softmax, OOV zeros)
// ---------------------------------------------------------------------------
__global__ void final_vocab_kernel(const float* __restrict__ logits,
                                   const float* __restrict__ rowm,
                                   const float* __restrict__ rows,
                                   const float* __restrict__ pgen,
                                   float* __restrict__ outf)
{
    long idx = (long)blockIdx.x * blockDim.x + threadIdx.x;
    if (idx >= (long)BB * VEXTN) return;
    int b = (int)(idx / VEXTN);
    int n = (int)(idx % VEXTN);
    float val = 0.f;
    if (n < VV) {
        float scale = pgen[b] / rows[b];
        val = scale * __expf(logits[(size_t)b * VV + n] - rowm[b]);
    }
    outf[idx] = val;
}

// ---------------------------------------------------------------------------
// Copy-mechanism scatter
// ---------------------------------------------------------------------------
__global__ void scatter_kernel(const int* __restrict__ ids,
                               const float* __restrict__ attn,
                               const float* __restrict__ pgen,
                               float* __restrict__ outf)
{
    int idx = blockIdx.x * blockDim.x + threadIdx.x;
    if (idx >= BB * SS) return;
    int b = idx / SS;
    float v = (1.f - pgen[b]) * attn[idx];
    atomicAdd(&outf[(size_t)b * VEXTN + ids[idx]], v);
}

// ---------------------------------------------------------------------------
// Launcher
// ---------------------------------------------------------------------------
extern "C" void kernel_launch(void* const* d_in, const int* in_sizes, int n_in,
                              void* d_out, int out_size)
{
    const float* emb    = (const float*)d_in[0];
    const float* feed   = (const float*)d_in[1];
    const float* hidden = (const float*)d_in[2];
    const float* ctx0   = (const float*)d_in[3];
    const float* states = (const float*)d_in[4];
    const float* sfeat  = (const float*)d_in[5];
    const float* mask   = (const float*)d_in[6];
    const float* cov    = (const float*)d_in[7];
    const int*   srcids = (const int*)d_in[8];
    const float* W_ic   = (const float*)d_in[9];
    const float* b_ic   = (const float*)d_in[10];
    const float* W_ih   = (const float*)d_in[11];
    const float* W_hh   = (const float*)d_in[12];
    const float* b_ih   = (const float*)d_in[13];
    const float* b_hh   = (const float*)d_in[14];
    const float* W_dec  = (const float*)d_in[15];
    const float* b_att  = (const float*)d_in[16];
    const float* v_att  = (const float*)d_in[17];
    const float* w_c    = (const float*)d_in[18];
    const float* W_out  = (const float*)d_in[19];
    const float* b_out  = (const float*)d_in[20];
    const float* W_pg   = (const float*)d_in[21];
    const float* b_pg   = (const float*)d_in[22];
    const float* W_v    = (const float*)d_in[23];
    const float* b_v    = (const float*)d_in[24];

    float* out = (float*)d_out;
    float* out_final = out;
    float* out_pgen  = out_final + (size_t)BB * VEXTN;
    float* out_attn  = out_pgen + BB;
    float* out_cov   = out_attn + (size_t)BB * SS;
    float* out_h1    = out_cov + (size_t)BB * SS;
    float* out_c1    = out_h1 + (size_t)BB * HH;
    float* out_dec   = out_c1 + (size_t)BB * HH;

    float *px, *pgates, *ph1, *pc1, *pdecfea, *pctx, *pdecout;
    float *pe, *pattn, *ppgen, *prowm, *prows, *plogits, *ppmax, *ppsum;
    __nv_bfloat16* pdecbf;
    cudaGetSymbolAddress((void**)&px,      g_x);
    cudaGetSymbolAddress((void**)&pgates,  g_gates);
    cudaGetSymbolAddress((void**)&ph1,     g_h1);
    cudaGetSymbolAddress((void**)&pc1,     g_c1);
    cudaGetSymbolAddress((void**)&pdecfea, g_decfea);
    cudaGetSymbolAddress((void**)&pctx,    g_ctx);
    cudaGetSymbolAddress((void**)&pdecout, g_decout);
    cudaGetSymbolAddress((void**)&pdecbf,  g_dec_bf);
    cudaGetSymbolAddress((void**)&pe,      g_e);
    cudaGetSymbolAddress((void**)&pattn,   g_attn);
    cudaGetSymbolAddress((void**)&ppgen,   g_pgen);
    cudaGetSymbolAddress((void**)&prowm,   g_rowm);
    cudaGetSymbolAddress((void**)&prows,   g_rows);
    cudaGetSymbolAddress((void**)&ppmax,   g_pmax);
    cudaGetSymbolAddress((void**)&ppsum,   g_psum);
    cudaGetSymbolAddress((void**)&plogits, g_logits);

    // 0) fused init (bias fills + ctx zero)
    fill_bias_all<<<524288 / 256, 256>>>(px, b_ic, pgates, b_ih,
                                         pdecfea, b_att, pdecout, b_out, pctx);

    // 1) x = [emb|feed] @ W_ic^T   (tf32, split 8)
    gemm_tf32_splitk<<<dim3(EE / 64, 1, 8), 256>>>(
        EE, 1024, 128, emb, EE, feed, W_ic, 1024, nullptr, px);

    // 2) gates = [x|h0] @ [W_ih|W_hh]^T   (tf32, split 8)
    gemm_tf32_splitk<<<dim3(4 * HH / 64, 1, 8), 256>>>(
        4 * HH, 1024, 128, px, EE, hidden, W_ih, EE, W_hh, pgates);

    // 3) LSTM elementwise (vectorized)
    lstm_elem<<<(BB * HH / 4 + 255) / 256, 256>>>(pgates, b_hh, ctx0, ph1, pc1,
                                                  out_h1, out_c1);

    // 4) dec_fea = h1 @ W_dec^T   (tf32, split 8)
    gemm_tf32_splitk<<<dim3(HH / 64, 1, 8), 256>>>(
        HH, 512, 64, ph1, 512, nullptr, W_dec, 512, nullptr, pdecfea);

    // 5) attention energies
    attn_e_kernel<<<(BB * SS) / 8, 256>>>(sfeat, pdecfea, cov, mask, v_att, w_c, pe);

    // 6) softmax over S + coverage update
    softmax_s_kernel<<<BB, 512>>>(pe, mask, cov, pattn, out_attn, out_cov);

    // 7) context vector (split-S x4, atomic reduce)
    ctx_kernel<<<dim3(BB, 2, CSPLIT), 256>>>(pattn, states, pctx);

    // 8) dec_out = [h1|ctx] @ W_out^T   (tf32, split 8)
    gemm_tf32_splitk<<<dim3(HH / 64, 1, 8), 256>>>(
        HH, 1024, 128, ph1, HH, pctx, W_out, 1024, nullptr, pdecout);

    // 9) p_gen + dec_out output copy + bf16 convert
    pgen_kernel<<<BB, 128>>>(pdecout, W_pg, b_pg, ppgen, out_pgen, out_dec, pdecbf);

    // 10) vocab logits (bf16 MMA) + fused softmax partials
    vocab_gemm_mma<<<NPB, 256>>>(pdecbf, W_v, b_v, plogits, ppmax, ppsum);

    // 11) reduce softmax partials
    reduce_stats_kernel<<<BB, 256>>>(ppmax, ppsum, prowm, prows);

    // 12) final vocab distribution (incl. zero OOV tail)
    {
        long total = (long)BB * VEXTN;
        final_vocab_kernel<<<(int)((total + 255) / 256), 256>>>(
            plogits, prowm, prows, ppgen, out_final);
    }

    // 13) copy scatter
    scatter_kernel<<<(BB * SS + 255) / 256, 256>>>(srcids, pattn, ppgen, out_final);
}